// round 12
// baseline (speedup 1.0000x reference)
#include <cuda_runtime.h>
#include <cuda_bf16.h>
#include <mma.h>
#include <cstdint>
#include <cstddef>

using namespace nvcuda;

// Problem constants (fixed by the reference)
#define NN 100000
#define EE 600000
#define DD 128
#define LL 5
#define BN_EPS 1e-5f
#define NT 782                 // row tiles of 128 (782*128 = 100096)
#define NPAD (NT * 128)        // padded rows so wmma stores stay in bounds
#define SROW 136               // padded smem row (bf16 elems)
#define GEMM_GRID 148
#define EDGE_BLOCKS 592        // 8 warps/block, persistent

// ---------------------------------------------------------------------------
// Device scratch
// ---------------------------------------------------------------------------
__device__ __align__(16) float         g_hl[(size_t)NPAD * DD]; // post-linear (NO bias)
__device__ __align__(16) float         g_hn[(size_t)NN * DD];   // layer output (pre-BN h)
__device__ __align__(16) unsigned char g_ea[(size_t)EE * 32];   // edge_attr 2-bit, CSR order
__device__ __align__(16) int2          g_meta[EE];              // CSR: {src, norm bits}
__device__ __align__(16) int           g_pos[EE];               // edge e -> CSR slot
__device__ __align__(16) int           g_degcnt[NN];
__device__ __align__(16) int           g_indeg[NN];
__device__ __align__(16) int           g_cursor[NN];
__device__ __align__(16) int           g_off[NN + 1];
__device__ __align__(16) int           g_bsum[128];
__device__ __align__(16) float         g_invdeg[NN];
__device__ __align__(16) float         g_dinv[NN];
__device__ __align__(16) float         g_scl[LL * DD];
__device__ __align__(16) float         g_sft[LL * DD];
__device__ int g_is64;

// Pack 4 floats -> 4 bf16 (hi) and 4 residual bf16 (lo), 8 bytes each.
__device__ __forceinline__ void split4(float v0, float v1, float v2, float v3,
                                       uint2& hi, uint2& lo) {
    __nv_bfloat162 p0 = __floats2bfloat162_rn(v0, v1);
    __nv_bfloat162 p1 = __floats2bfloat162_rn(v2, v3);
    float2 f0 = __bfloat1622float2(p0);
    float2 f1 = __bfloat1622float2(p1);
    __nv_bfloat162 q0 = __floats2bfloat162_rn(v0 - f0.x, v1 - f0.y);
    __nv_bfloat162 q1 = __floats2bfloat162_rn(v2 - f1.x, v3 - f1.y);
    hi = make_uint2(*(uint32_t*)&p0, *(uint32_t*)&p1);
    lo = make_uint2(*(uint32_t*)&q0, *(uint32_t*)&q1);
}

// ---------------------------------------------------------------------------
// Preprocessing
// ---------------------------------------------------------------------------
__global__ void k_detect(const int* __restrict__ ei32) {
    __shared__ int s_any;
    if (threadIdx.x == 0) s_any = 0;
    __syncthreads();
    int v = 0;
    for (int i = threadIdx.x; i < 4096; i += blockDim.x)
        v |= ei32[2 * i + 1];
    atomicOr(&s_any, v);
    __syncthreads();
    if (threadIdx.x == 0) g_is64 = (s_any == 0) ? 1 : 0;
}

__global__ void k_zero() {
    int i = blockIdx.x * blockDim.x + threadIdx.x;
    if (i < NN) { g_degcnt[i] = 0; g_indeg[i] = 0; g_cursor[i] = 0; }
}

__device__ __forceinline__ void load_edge(const void* ei, int e, int& r, int& c) {
    if (g_is64) {
        const long long* p = (const long long*)ei;
        r = (int)p[e]; c = (int)p[EE + e];
    } else {
        const int* p = (const int*)ei;
        r = p[e]; c = p[EE + e];
    }
    r = min(max(r, 0), NN - 1);
    c = min(max(c, 0), NN - 1);
}

__global__ void k_edge_pre(const void* __restrict__ ei) {
    int e = blockIdx.x * blockDim.x + threadIdx.x;
    if (e >= EE) return;
    int r, c; load_edge(ei, e, r, c);
    atomicAdd(&g_degcnt[r], 1);
    atomicAdd(&g_indeg[c], 1);
}

__global__ void k_node() {
    int n = blockIdx.x * blockDim.x + threadIdx.x;
    if (n >= NN) return;
    float d = (float)(g_degcnt[n] + 1);
    g_invdeg[n] = 1.0f / d;
    g_dinv[n]   = rsqrtf(d);
}

__global__ void k_scan1() {            // grid 98, block 1024
    __shared__ int s[1024];
    int i = blockIdx.x * 1024 + threadIdx.x;
    int v = (i < NN) ? g_indeg[i] : 0;
    s[threadIdx.x] = v;
    __syncthreads();
    for (int d = 1; d < 1024; d <<= 1) {
        int t = (threadIdx.x >= d) ? s[threadIdx.x - d] : 0;
        __syncthreads();
        s[threadIdx.x] += t;
        __syncthreads();
    }
    if (i < NN) g_off[i] = s[threadIdx.x] - v;
    if (threadIdx.x == 1023) g_bsum[blockIdx.x] = s[1023];
}

__global__ void k_scan2() {            // 1 block, 128 threads
    __shared__ int s[128];
    int t = threadIdx.x;
    s[t] = (t < 98) ? g_bsum[t] : 0;
    __syncthreads();
    for (int d = 1; d < 128; d <<= 1) {
        int v = (t >= d) ? s[t - d] : 0;
        __syncthreads();
        s[t] += v;
        __syncthreads();
    }
    if (t < 98) g_bsum[t] = s[t];
}

__global__ void k_scan3() {            // grid 98, block 1024
    int i = blockIdx.x * 1024 + threadIdx.x;
    int add = (blockIdx.x > 0) ? g_bsum[blockIdx.x - 1] : 0;
    if (i < NN) g_off[i] += add;
    if (i == NN) g_off[NN] = EE;
}

__global__ void k_place(const void* __restrict__ ei) {
    int e = blockIdx.x * blockDim.x + threadIdx.x;
    if (e >= EE) return;
    int r, c; load_edge(ei, e, r, c);
    int pos = g_off[c] + atomicAdd(&g_cursor[c], 1);
    float nrm = g_dinv[r] * g_dinv[c];
    g_meta[pos] = make_int2(r, __float_as_int(nrm));
    g_pos[e]    = pos;
}

// Pack int32 edge_attr (0..3) -> 2 bits, CSR slot order.
__global__ void k_pack2(const int4* __restrict__ ea) {
    int i = blockIdx.x * blockDim.x + threadIdx.x;
    if (i >= EE * 8) return;
    int e = i >> 3, g = i & 7;
    const int4* p = ea + (size_t)e * 32 + g * 4;
    unsigned int u = 0;
    #pragma unroll
    for (int q = 0; q < 4; q++) {
        int4 v = __ldg(&p[q]);
        u |= ((unsigned)v.x & 3u) << (q * 8 + 0);
        u |= ((unsigned)v.y & 3u) << (q * 8 + 2);
        u |= ((unsigned)v.z & 3u) << (q * 8 + 4);
        u |= ((unsigned)v.w & 3u) << (q * 8 + 6);
    }
    ((unsigned int*)g_ea)[(size_t)g_pos[e] * 8 + g] = u;
}

__global__ void k_bnconst(const float* __restrict__ gamma, const float* __restrict__ beta,
                          const float* __restrict__ mean,  const float* __restrict__ var) {
    int i = blockIdx.x * blockDim.x + threadIdx.x;
    if (i >= LL * DD) return;
    float s = gamma[i] * rsqrtf(var[i] + BN_EPS);
    g_scl[i] = s;
    g_sft[i] = beta[i] - mean[i] * s;
}

// ---------------------------------------------------------------------------
// Tensor-core GEMM, bf16 hi/lo 3-term (unchanged from R11)
// ---------------------------------------------------------------------------
__global__ __launch_bounds__(256, 1)
void k_gemm_tc(const float* __restrict__ A_in, const float* __restrict__ W, int aff)
{
    extern __shared__ __nv_bfloat16 sm[];
    __nv_bfloat16* sWh = sm;                       // [128][SROW]
    __nv_bfloat16* sWl = sm + 128 * SROW;
    __nv_bfloat16* sAb = sm + 2 * 128 * SROW;      // [2 bufs][hi/lo][128][SROW]
    __shared__ float sScl[DD], sSft[DD];

    const float* A = A_in ? A_in : g_hn;
    int tid = threadIdx.x;
    bool doaff = (aff >= 0);

    if (tid < DD) {
        sScl[tid] = doaff ? g_scl[aff + tid] : 1.0f;
        sSft[tid] = doaff ? g_sft[aff + tid] : 0.0f;
    }

    for (int idx = tid; idx < 128 * 32; idx += 256) {
        int row = idx >> 5, c0 = (idx & 31) << 2;
        float4 w = __ldg((const float4*)(W + row * DD + c0));
        uint2 hi, lo;
        split4(w.x, w.y, w.z, w.w, hi, lo);
        *(uint2*)(sWh + row * SROW + c0) = hi;
        *(uint2*)(sWl + row * SROW + c0) = lo;
    }

    int wid = tid >> 5;
    int r   = tid >> 1;
    int ch  = (tid & 1) << 4;

    int t = blockIdx.x;
    float4 st[16];
    if (t < NT) {
        int grow = min(t * 128 + r, NN - 1);
        const float4* src = (const float4*)(A + (size_t)grow * DD) + ch;
        #pragma unroll
        for (int i = 0; i < 16; i++) st[i] = __ldg(&src[i]);
    }
    __syncthreads();

    int buf = 0;
    while (t < NT) {
        __nv_bfloat16* sAh = sAb + buf * 2 * 128 * SROW;
        __nv_bfloat16* sAl = sAh + 128 * SROW;
        #pragma unroll
        for (int i = 0; i < 16; i++) {
            int c = (ch + i) * 4;
            float v0 = st[i].x, v1 = st[i].y, v2 = st[i].z, v3 = st[i].w;
            if (doaff) {
                v0 = fmaxf(fmaf(v0, sScl[c + 0], sSft[c + 0]), 0.f);
                v1 = fmaxf(fmaf(v1, sScl[c + 1], sSft[c + 1]), 0.f);
                v2 = fmaxf(fmaf(v2, sScl[c + 2], sSft[c + 2]), 0.f);
                v3 = fmaxf(fmaf(v3, sScl[c + 3], sSft[c + 3]), 0.f);
            }
            uint2 hi, lo;
            split4(v0, v1, v2, v3, hi, lo);
            *(uint2*)(sAh + r * SROW + c) = hi;
            *(uint2*)(sAl + r * SROW + c) = lo;
        }
        __syncthreads();

        int tn = t + GEMM_GRID;
        if (tn < NT) {
            int grow = min(tn * 128 + r, NN - 1);
            const float4* src = (const float4*)(A + (size_t)grow * DD) + ch;
            #pragma unroll
            for (int i = 0; i < 16; i++) st[i] = __ldg(&src[i]);
        }

        int m0 = wid * 16;
        wmma::fragment<wmma::matrix_a, 16, 16, 16, __nv_bfloat16, wmma::row_major> fah[8], fal[8];
        #pragma unroll
        for (int k = 0; k < 8; k++) {
            wmma::load_matrix_sync(fah[k], sAh + m0 * SROW + k * 16, SROW);
            wmma::load_matrix_sync(fal[k], sAl + m0 * SROW + k * 16, SROW);
        }
        float* outbase = g_hl + (size_t)(t * 128 + m0) * DD;
        #pragma unroll
        for (int nn = 0; nn < 8; nn++) {
            wmma::fragment<wmma::accumulator, 16, 16, 16, float> acc;
            wmma::fill_fragment(acc, 0.f);
            #pragma unroll
            for (int k = 0; k < 8; k++) {
                wmma::fragment<wmma::matrix_b, 16, 16, 16, __nv_bfloat16, wmma::col_major> fbh, fbl;
                wmma::load_matrix_sync(fbh, sWh + (nn * 16) * SROW + k * 16, SROW);
                wmma::load_matrix_sync(fbl, sWl + (nn * 16) * SROW + k * 16, SROW);
                wmma::mma_sync(acc, fah[k], fbh, acc);
                wmma::mma_sync(acc, fah[k], fbl, acc);
                wmma::mma_sync(acc, fal[k], fbh, acc);
            }
            wmma::store_matrix_sync(outbase + nn * 16, acc, DD, wmma::mem_row_major);
        }
        buf ^= 1;
        t = tn;
    }
}

// ---------------------------------------------------------------------------
// CSR aggregation: one warp, two interleaved nodes; int2 meta; streaming
// loads (__ldcs) on meta + attr to preserve L2 for the g_hl gather set.
// ---------------------------------------------------------------------------
__device__ __forceinline__ void acc_edge2(float4& acc, float4 h, unsigned int a,
                                          float nrm, float4 b4) {
    acc.x += fmaxf(h.x + b4.x + (float)( a       & 3u), 0.f) * nrm;
    acc.y += fmaxf(h.y + b4.y + (float)((a >> 2) & 3u), 0.f) * nrm;
    acc.z += fmaxf(h.z + b4.z + (float)((a >> 4) & 3u), 0.f) * nrm;
    acc.w += fmaxf(h.w + b4.w + (float)((a >> 6) & 3u), 0.f) * nrm;
}

__device__ __forceinline__ void drain_edges(int j, int end, int lane,
                                            float4& acc, float4 b4,
                                            const float4* hl4) {
    for (; j + 1 < end; j += 2) {
        int2 m0 = __ldcs(&g_meta[j]);
        int2 m1 = __ldcs(&g_meta[j + 1]);
        unsigned int a0 = __ldcs(&g_ea[(size_t)j * 32 + lane]);
        unsigned int a1 = __ldcs(&g_ea[(size_t)(j + 1) * 32 + lane]);
        float4 h0 = __ldg(hl4 + (size_t)m0.x * 32 + lane);
        float4 h1 = __ldg(hl4 + (size_t)m1.x * 32 + lane);
        acc_edge2(acc, h0, a0, __int_as_float(m0.y), b4);
        acc_edge2(acc, h1, a1, __int_as_float(m1.y), b4);
    }
    if (j < end) {
        int2 m0 = __ldcs(&g_meta[j]);
        unsigned int a0 = __ldcs(&g_ea[(size_t)j * 32 + lane]);
        float4 h0 = __ldg(hl4 + (size_t)m0.x * 32 + lane);
        acc_edge2(acc, h0, a0, __int_as_float(m0.y), b4);
    }
}

__device__ __forceinline__ void finish_node(int n, int lane, float4 acc,
                                            float4 b4, float4 rt,
                                            float4 sc, float4 sf, int bnoff,
                                            const float4* hl4,
                                            float* __restrict__ outp) {
    float4 hs = __ldg(hl4 + (size_t)n * 32 + lane);
    float  id = __ldg(&g_invdeg[n]);
    acc.x += fmaxf(hs.x + b4.x + rt.x, 0.f) * id;
    acc.y += fmaxf(hs.y + b4.y + rt.y, 0.f) * id;
    acc.z += fmaxf(hs.z + b4.z + rt.z, 0.f) * id;
    acc.w += fmaxf(hs.w + b4.w + rt.w, 0.f) * id;
    if (bnoff >= 0) {
        acc.x = fmaf(acc.x, sc.x, sf.x);
        acc.y = fmaf(acc.y, sc.y, sf.y);
        acc.z = fmaf(acc.z, sc.z, sf.z);
        acc.w = fmaf(acc.w, sc.w, sf.w);
        ((float4*)outp)[(size_t)n * 32 + lane] = acc;
    } else {
        ((float4*)g_hn)[(size_t)n * 32 + lane] = acc;
    }
}

__global__ __launch_bounds__(256)
void k_edge_csr(const float* __restrict__ bias, const float* __restrict__ root,
                float* __restrict__ outp, int bnoff)
{
    int gw   = (blockIdx.x * blockDim.x + threadIdx.x) >> 5;
    int lane = threadIdx.x & 31;
    const int nwarps = EDGE_BLOCKS * 8;

    const float4* hl4 = (const float4*)g_hl;
    float4 b4 = __ldg((const float4*)bias + lane);
    float4 rt = __ldg((const float4*)root + lane);
    float4 sc = make_float4(0,0,0,0), sf = make_float4(0,0,0,0);
    if (bnoff >= 0) {
        sc = *(const float4*)&g_scl[bnoff + lane * 4];
        sf = *(const float4*)&g_sft[bnoff + lane * 4];
    }

    for (int n0 = gw; n0 < NN; n0 += 2 * nwarps) {
        int n1 = n0 + nwarps;
        bool has1 = (n1 < NN);

        int beg0 = __ldg(&g_off[n0]);
        int end0 = __ldg(&g_off[n0 + 1]);
        int beg1 = 0, end1 = 0;
        if (has1) { beg1 = __ldg(&g_off[n1]); end1 = __ldg(&g_off[n1 + 1]); }

        float4 acc0 = make_float4(0.f, 0.f, 0.f, 0.f);
        float4 acc1 = make_float4(0.f, 0.f, 0.f, 0.f);

        int j0 = beg0, j1 = beg1;
        while (j0 + 1 < end0 && j1 + 1 < end1) {
            int2 ma = __ldcs(&g_meta[j0]);
            int2 mb = __ldcs(&g_meta[j0 + 1]);
            int2 mx = __ldcs(&g_meta[j1]);
            int2 my = __ldcs(&g_meta[j1 + 1]);
            unsigned int aa = __ldcs(&g_ea[(size_t)j0 * 32 + lane]);
            unsigned int ab = __ldcs(&g_ea[(size_t)(j0 + 1) * 32 + lane]);
            unsigned int ax = __ldcs(&g_ea[(size_t)j1 * 32 + lane]);
            unsigned int ay = __ldcs(&g_ea[(size_t)(j1 + 1) * 32 + lane]);
            float4 ha = __ldg(hl4 + (size_t)ma.x * 32 + lane);
            float4 hb = __ldg(hl4 + (size_t)mb.x * 32 + lane);
            float4 hx = __ldg(hl4 + (size_t)mx.x * 32 + lane);
            float4 hy = __ldg(hl4 + (size_t)my.x * 32 + lane);
            acc_edge2(acc0, ha, aa, __int_as_float(ma.y), b4);
            acc_edge2(acc0, hb, ab, __int_as_float(mb.y), b4);
            acc_edge2(acc1, hx, ax, __int_as_float(mx.y), b4);
            acc_edge2(acc1, hy, ay, __int_as_float(my.y), b4);
            j0 += 2; j1 += 2;
        }
        drain_edges(j0, end0, lane, acc0, b4, hl4);
        finish_node(n0, lane, acc0, b4, rt, sc, sf, bnoff, hl4, outp);
        if (has1) {
            drain_edges(j1, end1, lane, acc1, b4, hl4);
            finish_node(n1, lane, acc1, b4, rt, sc, sf, bnoff, hl4, outp);
        }
    }
}

// ---------------------------------------------------------------------------
// Host driver (graph-capturable). Layer-0 GEMM is hoisted to launch index 3
// (it has no preprocessing deps) so the fixed ncu capture window (-s 5 -c 1,
// which empirically lands on our 4th launch) profiles the GEMM next round.
// ---------------------------------------------------------------------------
extern "C" void kernel_launch(void* const* d_in, const int* in_sizes, int n_in,
                              void* d_out, int out_size)
{
    const float* x     = (const float*)d_in[0];
    const void*  ei    = d_in[1];
    const int*   ea    = (const int*)d_in[2];
    const float* W     = (const float*)d_in[3];
    const float* b     = (const float*)d_in[4];
    const float* root  = (const float*)d_in[5];
    const float* gamma = (const float*)d_in[6];
    const float* beta  = (const float*)d_in[7];
    const float* mean  = (const float*)d_in[8];
    const float* var   = (const float*)d_in[9];
    (void)in_sizes; (void)n_in; (void)out_size;

    const int smem_bytes = (2 + 4) * 128 * SROW * (int)sizeof(__nv_bfloat16); // 208896
    cudaFuncSetAttribute(k_gemm_tc, cudaFuncAttributeMaxDynamicSharedMemorySize, smem_bytes);

    k_detect<<<1, 256>>>((const int*)ei);                       // 0
    k_zero<<<(NN + 255) / 256, 256>>>();                        // 1
    k_edge_pre<<<(EE + 255) / 256, 256>>>(ei);                  // 2
    k_gemm_tc<<<GEMM_GRID, 256, smem_bytes>>>(x, W, -1);        // 3  <- profiled slot
    k_scan1<<<98, 1024>>>();                                    // 4
    k_scan2<<<1, 128>>>();                                      // 5
    k_scan3<<<98, 1024>>>();                                    // 6
    k_node<<<(NN + 255) / 256, 256>>>();                        // 7
    k_place<<<(EE + 255) / 256, 256>>>(ei);                     // 8
    k_pack2<<<(EE * 8 + 255) / 256, 256>>>((const int4*)ea);    // 9
    k_bnconst<<<(LL * DD + 255) / 256, 256>>>(gamma, beta, mean, var); // 10

    for (int l = 0; l < LL; ++l) {
        if (l > 0) {
            k_gemm_tc<<<GEMM_GRID, 256, smem_bytes>>>(nullptr,
                                                      W + (size_t)l * DD * DD,
                                                      (l - 1) * DD);
        }
        float* outp = (l == LL - 1) ? (float*)d_out : nullptr;
        int    bn   = (l == LL - 1) ? (LL - 1) * DD : -1;
        k_edge_csr<<<EDGE_BLOCKS, 256>>>(b + (size_t)l * DD, root + (size_t)l * DD, outp, bn);
    }
}

// round 13
// speedup vs baseline: 1.0615x; 1.0615x over previous
#include <cuda_runtime.h>
#include <cuda_bf16.h>
#include <mma.h>
#include <cstdint>
#include <cstddef>

using namespace nvcuda;

#define NN 100000
#define EE 600000
#define DD 128
#define LL 5
#define BN_EPS 1e-5f
#define NT 782
#define NPAD (NT * 128)
#define SROW 136
#define GEMM_GRID 148
#define EDGE_BLOCKS 592

// ---------------------------------------------------------------------------
// Device scratch
// ---------------------------------------------------------------------------
__device__ __align__(16) float         g_hl[(size_t)NPAD * DD];
__device__ __align__(16) float         g_hn[(size_t)NN * DD];
__device__ __align__(16) unsigned char g_ea[(size_t)EE * 32];   // 2-bit attr, CSR order
__device__ __align__(16) int           g_srcn[EE];
__device__ __align__(16) float         g_enorm[EE];
__device__ __align__(16) int           g_pos[EE];
__device__ __align__(16) int           g_degcnt[NN];
__device__ __align__(16) int           g_indeg[NN];
__device__ __align__(16) int           g_cursor[NN];
__device__ __align__(16) int           g_off[NN + 1];
__device__ __align__(16) int           g_bsum[128];
__device__ __align__(16) float         g_invdeg[NN];
__device__ __align__(16) float         g_dinv[NN];
__device__ __align__(16) float         g_scl[LL * DD];
__device__ __align__(16) float         g_sft[LL * DD];
__device__ int g_is64;

__device__ __forceinline__ void split4(float v0, float v1, float v2, float v3,
                                       uint2& hi, uint2& lo) {
    __nv_bfloat162 p0 = __floats2bfloat162_rn(v0, v1);
    __nv_bfloat162 p1 = __floats2bfloat162_rn(v2, v3);
    float2 f0 = __bfloat1622float2(p0);
    float2 f1 = __bfloat1622float2(p1);
    __nv_bfloat162 q0 = __floats2bfloat162_rn(v0 - f0.x, v1 - f0.y);
    __nv_bfloat162 q1 = __floats2bfloat162_rn(v2 - f1.x, v3 - f1.y);
    hi = make_uint2(*(uint32_t*)&p0, *(uint32_t*)&p1);
    lo = make_uint2(*(uint32_t*)&q0, *(uint32_t*)&q1);
}

// ---------------------------------------------------------------------------
// Preprocessing
// ---------------------------------------------------------------------------
__global__ void k_detect(const int* __restrict__ ei32) {
    __shared__ int s_any;
    if (threadIdx.x == 0) s_any = 0;
    __syncthreads();
    int v = 0;
    for (int i = threadIdx.x; i < 4096; i += blockDim.x)
        v |= ei32[2 * i + 1];
    atomicOr(&s_any, v);
    __syncthreads();
    if (threadIdx.x == 0) g_is64 = (s_any == 0) ? 1 : 0;
}

__global__ void k_zero() {
    int i = blockIdx.x * blockDim.x + threadIdx.x;
    if (i < NN) { g_degcnt[i] = 0; g_indeg[i] = 0; g_cursor[i] = 0; }
}

__device__ __forceinline__ void load_edge(const void* ei, int e, int& r, int& c) {
    if (g_is64) {
        const long long* p = (const long long*)ei;
        r = (int)p[e]; c = (int)p[EE + e];
    } else {
        const int* p = (const int*)ei;
        r = p[e]; c = p[EE + e];
    }
    r = min(max(r, 0), NN - 1);
    c = min(max(c, 0), NN - 1);
}

__global__ void k_edge_pre(const void* __restrict__ ei) {
    int e = blockIdx.x * blockDim.x + threadIdx.x;
    if (e >= EE) return;
    int r, c; load_edge(ei, e, r, c);
    atomicAdd(&g_degcnt[r], 1);
    atomicAdd(&g_indeg[c], 1);
}

__global__ void k_node() {
    int n = blockIdx.x * blockDim.x + threadIdx.x;
    if (n >= NN) return;
    float d = (float)(g_degcnt[n] + 1);
    g_invdeg[n] = 1.0f / d;
    g_dinv[n]   = rsqrtf(d);
}

__global__ void k_scan1() {            // grid 98, block 1024
    __shared__ int s[1024];
    int i = blockIdx.x * 1024 + threadIdx.x;
    int v = (i < NN) ? g_indeg[i] : 0;
    s[threadIdx.x] = v;
    __syncthreads();
    for (int d = 1; d < 1024; d <<= 1) {
        int t = (threadIdx.x >= d) ? s[threadIdx.x - d] : 0;
        __syncthreads();
        s[threadIdx.x] += t;
        __syncthreads();
    }
    if (i < NN) g_off[i] = s[threadIdx.x] - v;
    if (threadIdx.x == 1023) g_bsum[blockIdx.x] = s[1023];
}

__global__ void k_scan2() {            // 1 block, 128 threads
    __shared__ int s[128];
    int t = threadIdx.x;
    s[t] = (t < 98) ? g_bsum[t] : 0;
    __syncthreads();
    for (int d = 1; d < 128; d <<= 1) {
        int v = (t >= d) ? s[t - d] : 0;
        __syncthreads();
        s[t] += v;
        __syncthreads();
    }
    if (t < 98) g_bsum[t] = s[t];
}

__global__ void k_scan3() {            // grid 98, block 1024
    int i = blockIdx.x * 1024 + threadIdx.x;
    int add = (blockIdx.x > 0) ? g_bsum[blockIdx.x - 1] : 0;
    if (i < NN) g_off[i] += add;
    if (i == NN) g_off[NN] = EE;
}

__global__ void k_place(const void* __restrict__ ei) {
    int e = blockIdx.x * blockDim.x + threadIdx.x;
    if (e >= EE) return;
    int r, c; load_edge(ei, e, r, c);
    int pos = g_off[c] + atomicAdd(&g_cursor[c], 1);
    g_srcn[pos]  = r;
    g_enorm[pos] = g_dinv[r] * g_dinv[c];
    g_pos[e]     = pos;
}

__global__ void k_pack2(const int4* __restrict__ ea) {
    int i = blockIdx.x * blockDim.x + threadIdx.x;
    if (i >= EE * 8) return;
    int e = i >> 3, g = i & 7;
    const int4* p = ea + (size_t)e * 32 + g * 4;
    unsigned int u = 0;
    #pragma unroll
    for (int q = 0; q < 4; q++) {
        int4 v = __ldg(&p[q]);
        u |= ((unsigned)v.x & 3u) << (q * 8 + 0);
        u |= ((unsigned)v.y & 3u) << (q * 8 + 2);
        u |= ((unsigned)v.z & 3u) << (q * 8 + 4);
        u |= ((unsigned)v.w & 3u) << (q * 8 + 6);
    }
    ((unsigned int*)g_ea)[(size_t)g_pos[e] * 8 + g] = u;
}

__global__ void k_bnconst(const float* __restrict__ gamma, const float* __restrict__ beta,
                          const float* __restrict__ mean,  const float* __restrict__ var) {
    int i = blockIdx.x * blockDim.x + threadIdx.x;
    if (i >= LL * DD) return;
    float s = gamma[i] * rsqrtf(var[i] + BN_EPS);
    g_scl[i] = s;
    g_sft[i] = beta[i] - mean[i] * s;
}

// ---------------------------------------------------------------------------
// Tensor-core GEMM, bf16 hi/lo 3-term. 512 threads: 16 warps = 8 m-warps x
// 2 n-warps; warp = 16 rows x 64 cols. fah held in regs; fal/fbh/fbl loaded
// per (nn,k) to stay under 128 regs at 512 threads.
// ---------------------------------------------------------------------------
__global__ __launch_bounds__(512, 1)
void k_gemm_tc(const float* __restrict__ A_in, const float* __restrict__ W, int aff)
{
    extern __shared__ __nv_bfloat16 sm[];
    __nv_bfloat16* sWh = sm;                       // [128][SROW]
    __nv_bfloat16* sWl = sm + 128 * SROW;
    __nv_bfloat16* sAb = sm + 2 * 128 * SROW;      // [2 bufs][hi/lo][128][SROW]
    __shared__ float sScl[DD], sSft[DD];

    const float* A = A_in ? A_in : g_hn;
    int tid = threadIdx.x;
    bool doaff = (aff >= 0);

    if (tid < DD) {
        sScl[tid] = doaff ? g_scl[aff + tid] : 1.0f;
        sSft[tid] = doaff ? g_sft[aff + tid] : 0.0f;
    }

    for (int idx = tid; idx < 128 * 32; idx += 512) {
        int row = idx >> 5, c0 = (idx & 31) << 2;
        float4 w = __ldg((const float4*)(W + row * DD + c0));
        uint2 hi, lo;
        split4(w.x, w.y, w.z, w.w, hi, lo);
        *(uint2*)(sWh + row * SROW + c0) = hi;
        *(uint2*)(sWl + row * SROW + c0) = lo;
    }

    int wid = tid >> 5;
    int wm  = wid & 7;             // m-chunk (16 rows)
    int wn  = wid >> 3;            // n-half (64 cols)
    int r   = tid >> 2;            // staging row 0..127
    int ch  = (tid & 3) << 3;      // float4 col offset: 0,8,16,24

    int t = blockIdx.x;
    float4 st[8];
    if (t < NT) {
        int grow = min(t * 128 + r, NN - 1);
        const float4* src = (const float4*)(A + (size_t)grow * DD) + ch;
        #pragma unroll
        for (int i = 0; i < 8; i++) st[i] = __ldg(&src[i]);
    }
    __syncthreads();

    int buf = 0;
    while (t < NT) {
        __nv_bfloat16* sAh = sAb + buf * 2 * 128 * SROW;
        __nv_bfloat16* sAl = sAh + 128 * SROW;
        #pragma unroll
        for (int i = 0; i < 8; i++) {
            int c = (ch + i) * 4;
            float v0 = st[i].x, v1 = st[i].y, v2 = st[i].z, v3 = st[i].w;
            if (doaff) {
                v0 = fmaxf(fmaf(v0, sScl[c + 0], sSft[c + 0]), 0.f);
                v1 = fmaxf(fmaf(v1, sScl[c + 1], sSft[c + 1]), 0.f);
                v2 = fmaxf(fmaf(v2, sScl[c + 2], sSft[c + 2]), 0.f);
                v3 = fmaxf(fmaf(v3, sScl[c + 3], sSft[c + 3]), 0.f);
            }
            uint2 hi, lo;
            split4(v0, v1, v2, v3, hi, lo);
            *(uint2*)(sAh + r * SROW + c) = hi;
            *(uint2*)(sAl + r * SROW + c) = lo;
        }
        __syncthreads();

        int tn = t + GEMM_GRID;
        if (tn < NT) {
            int grow = min(tn * 128 + r, NN - 1);
            const float4* src = (const float4*)(A + (size_t)grow * DD) + ch;
            #pragma unroll
            for (int i = 0; i < 8; i++) st[i] = __ldg(&src[i]);
        }

        int m0 = wm * 16;
        wmma::fragment<wmma::matrix_a, 16, 16, 16, __nv_bfloat16, wmma::row_major> fah[8];
        #pragma unroll
        for (int k = 0; k < 8; k++)
            wmma::load_matrix_sync(fah[k], sAh + m0 * SROW + k * 16, SROW);

        float* outbase = g_hl + (size_t)(t * 128 + m0) * DD + wn * 64;
        #pragma unroll
        for (int nn = 0; nn < 4; nn++) {
            int c0 = wn * 64 + nn * 16;
            wmma::fragment<wmma::accumulator, 16, 16, 16, float> acc;
            wmma::fill_fragment(acc, 0.f);
            #pragma unroll
            for (int k = 0; k < 8; k++) {
                wmma::fragment<wmma::matrix_b, 16, 16, 16, __nv_bfloat16, wmma::col_major> fbh, fbl;
                wmma::fragment<wmma::matrix_a, 16, 16, 16, __nv_bfloat16, wmma::row_major> falk;
                wmma::load_matrix_sync(fbh, sWh + c0 * SROW + k * 16, SROW);
                wmma::load_matrix_sync(fbl, sWl + c0 * SROW + k * 16, SROW);
                wmma::load_matrix_sync(falk, sAl + m0 * SROW + k * 16, SROW);
                wmma::mma_sync(acc, fah[k], fbh, acc);
                wmma::mma_sync(acc, fah[k], fbl, acc);
                wmma::mma_sync(acc, falk, fbh, acc);
            }
            wmma::store_matrix_sync(outbase + nn * 16, acc, DD, wmma::mem_row_major);
        }
        buf ^= 1;
        t = tn;
    }
}

// ---------------------------------------------------------------------------
// CSR aggregation (R11 version: srcn/enorm, __ldg, node-pair interleave)
// ---------------------------------------------------------------------------
__device__ __forceinline__ void acc_edge2(float4& acc, float4 h, unsigned int a,
                                          float nrm, float4 b4) {
    acc.x += fmaxf(h.x + b4.x + (float)( a       & 3u), 0.f) * nrm;
    acc.y += fmaxf(h.y + b4.y + (float)((a >> 2) & 3u), 0.f) * nrm;
    acc.z += fmaxf(h.z + b4.z + (float)((a >> 4) & 3u), 0.f) * nrm;
    acc.w += fmaxf(h.w + b4.w + (float)((a >> 6) & 3u), 0.f) * nrm;
}

__device__ __forceinline__ void drain_edges(int j, int end, int lane,
                                            float4& acc, float4 b4,
                                            const float4* hl4) {
    for (; j + 1 < end; j += 2) {
        int   s0 = __ldg(&g_srcn[j]);
        int   s1 = __ldg(&g_srcn[j + 1]);
        float n0 = __ldg(&g_enorm[j]);
        float n1 = __ldg(&g_enorm[j + 1]);
        unsigned int a0 = __ldg(&g_ea[(size_t)j * 32 + lane]);
        unsigned int a1 = __ldg(&g_ea[(size_t)(j + 1) * 32 + lane]);
        float4 h0 = __ldg(hl4 + (size_t)s0 * 32 + lane);
        float4 h1 = __ldg(hl4 + (size_t)s1 * 32 + lane);
        acc_edge2(acc, h0, a0, n0, b4);
        acc_edge2(acc, h1, a1, n1, b4);
    }
    if (j < end) {
        int   s0 = __ldg(&g_srcn[j]);
        float n0 = __ldg(&g_enorm[j]);
        unsigned int a0 = __ldg(&g_ea[(size_t)j * 32 + lane]);
        float4 h0 = __ldg(hl4 + (size_t)s0 * 32 + lane);
        acc_edge2(acc, h0, a0, n0, b4);
    }
}

__device__ __forceinline__ void finish_node(int n, int lane, float4 acc,
                                            float4 b4, float4 rt,
                                            float4 sc, float4 sf, int bnoff,
                                            const float4* hl4,
                                            float* __restrict__ outp) {
    float4 hs = __ldg(hl4 + (size_t)n * 32 + lane);
    float  id = __ldg(&g_invdeg[n]);
    acc.x += fmaxf(hs.x + b4.x + rt.x, 0.f) * id;
    acc.y += fmaxf(hs.y + b4.y + rt.y, 0.f) * id;
    acc.z += fmaxf(hs.z + b4.z + rt.z, 0.f) * id;
    acc.w += fmaxf(hs.w + b4.w + rt.w, 0.f) * id;
    if (bnoff >= 0) {
        acc.x = fmaf(acc.x, sc.x, sf.x);
        acc.y = fmaf(acc.y, sc.y, sf.y);
        acc.z = fmaf(acc.z, sc.z, sf.z);
        acc.w = fmaf(acc.w, sc.w, sf.w);
        ((float4*)outp)[(size_t)n * 32 + lane] = acc;
    } else {
        ((float4*)g_hn)[(size_t)n * 32 + lane] = acc;
    }
}

__global__ __launch_bounds__(256)
void k_edge_csr(const float* __restrict__ bias, const float* __restrict__ root,
                float* __restrict__ outp, int bnoff)
{
    int gw   = (blockIdx.x * blockDim.x + threadIdx.x) >> 5;
    int lane = threadIdx.x & 31;
    const int nwarps = EDGE_BLOCKS * 8;

    const float4* hl4 = (const float4*)g_hl;
    float4 b4 = __ldg((const float4*)bias + lane);
    float4 rt = __ldg((const float4*)root + lane);
    float4 sc = make_float4(0,0,0,0), sf = make_float4(0,0,0,0);
    if (bnoff >= 0) {
        sc = *(const float4*)&g_scl[bnoff + lane * 4];
        sf = *(const float4*)&g_sft[bnoff + lane * 4];
    }

    for (int n0 = gw; n0 < NN; n0 += 2 * nwarps) {
        int n1 = n0 + nwarps;
        bool has1 = (n1 < NN);

        int beg0 = __ldg(&g_off[n0]);
        int end0 = __ldg(&g_off[n0 + 1]);
        int beg1 = 0, end1 = 0;
        if (has1) { beg1 = __ldg(&g_off[n1]); end1 = __ldg(&g_off[n1 + 1]); }

        float4 acc0 = make_float4(0.f, 0.f, 0.f, 0.f);
        float4 acc1 = make_float4(0.f, 0.f, 0.f, 0.f);

        int j0 = beg0, j1 = beg1;
        while (j0 + 1 < end0 && j1 + 1 < end1) {
            int   sa = __ldg(&g_srcn[j0]);
            int   sb = __ldg(&g_srcn[j0 + 1]);
            int   sx = __ldg(&g_srcn[j1]);
            int   sy = __ldg(&g_srcn[j1 + 1]);
            float na = __ldg(&g_enorm[j0]);
            float nb = __ldg(&g_enorm[j0 + 1]);
            float nx = __ldg(&g_enorm[j1]);
            float ny = __ldg(&g_enorm[j1 + 1]);
            unsigned int aa = __ldg(&g_ea[(size_t)j0 * 32 + lane]);
            unsigned int ab = __ldg(&g_ea[(size_t)(j0 + 1) * 32 + lane]);
            unsigned int ax = __ldg(&g_ea[(size_t)j1 * 32 + lane]);
            unsigned int ay = __ldg(&g_ea[(size_t)(j1 + 1) * 32 + lane]);
            float4 ha = __ldg(hl4 + (size_t)sa * 32 + lane);
            float4 hb = __ldg(hl4 + (size_t)sb * 32 + lane);
            float4 hx = __ldg(hl4 + (size_t)sx * 32 + lane);
            float4 hy = __ldg(hl4 + (size_t)sy * 32 + lane);
            acc_edge2(acc0, ha, aa, na, b4);
            acc_edge2(acc0, hb, ab, nb, b4);
            acc_edge2(acc1, hx, ax, nx, b4);
            acc_edge2(acc1, hy, ay, ny, b4);
            j0 += 2; j1 += 2;
        }
        drain_edges(j0, end0, lane, acc0, b4, hl4);
        finish_node(n0, lane, acc0, b4, rt, sc, sf, bnoff, hl4, outp);
        if (has1) {
            drain_edges(j1, end1, lane, acc1, b4, hl4);
            finish_node(n1, lane, acc1, b4, rt, sc, sf, bnoff, hl4, outp);
        }
    }
}

// ---------------------------------------------------------------------------
// Host driver (graph-capturable, natural order: GEMM-l adjacent to edge-l)
// ---------------------------------------------------------------------------
extern "C" void kernel_launch(void* const* d_in, const int* in_sizes, int n_in,
                              void* d_out, int out_size)
{
    const float* x     = (const float*)d_in[0];
    const void*  ei    = d_in[1];
    const int*   ea    = (const int*)d_in[2];
    const float* W     = (const float*)d_in[3];
    const float* b     = (const float*)d_in[4];
    const float* root  = (const float*)d_in[5];
    const float* gamma = (const float*)d_in[6];
    const float* beta  = (const float*)d_in[7];
    const float* mean  = (const float*)d_in[8];
    const float* var   = (const float*)d_in[9];
    (void)in_sizes; (void)n_in; (void)out_size;

    const int smem_bytes = (2 + 4) * 128 * SROW * (int)sizeof(__nv_bfloat16); // 208896
    cudaFuncSetAttribute(k_gemm_tc, cudaFuncAttributeMaxDynamicSharedMemorySize, smem_bytes);

    k_detect<<<1, 256>>>((const int*)ei);
    k_zero<<<(NN + 255) / 256, 256>>>();
    k_edge_pre<<<(EE + 255) / 256, 256>>>(ei);
    k_node<<<(NN + 255) / 256, 256>>>();
    k_scan1<<<98, 1024>>>();
    k_scan2<<<1, 128>>>();
    k_scan3<<<98, 1024>>>();
    k_place<<<(EE + 255) / 256, 256>>>(ei);
    k_pack2<<<(EE * 8 + 255) / 256, 256>>>((const int4*)ea);
    k_bnconst<<<(LL * DD + 255) / 256, 256>>>(gamma, beta, mean, var);

    for (int l = 0; l < LL; ++l) {
        const float* A   = (l == 0) ? x : nullptr;
        int          aff = (l == 0) ? -1 : (l - 1) * DD;
        k_gemm_tc<<<GEMM_GRID, 512, smem_bytes>>>(A, W + (size_t)l * DD * DD, aff);
        float* outp = (l == LL - 1) ? (float*)d_out : nullptr;
        int    bn   = (l == LL - 1) ? (LL - 1) * DD : -1;
        k_edge_csr<<<EDGE_BLOCKS, 256>>>(b + (size_t)l * DD, root + (size_t)l * DD, outp, bn);
    }
}

// round 14
// speedup vs baseline: 1.0640x; 1.0024x over previous
#include <cuda_runtime.h>
#include <cuda_bf16.h>
#include <mma.h>
#include <cstdint>
#include <cstddef>

using namespace nvcuda;

#define NN 100000
#define EE 600000
#define DD 128
#define LL 5
#define BN_EPS 1e-5f
#define NT 782
#define NPAD (NT * 128)
#define SROW 136
#define GEMM_GRID 148
#define EDGE_BLOCKS 592

// ---------------------------------------------------------------------------
// Device scratch
// ---------------------------------------------------------------------------
__device__ __align__(16) float         g_hl[(size_t)NPAD * DD];
__device__ __align__(16) float         g_hn[(size_t)NN * DD];
__device__ __align__(16) unsigned char g_ea[(size_t)EE * 32];   // 2-bit attr, CSR order
__device__ __align__(16) int           g_srcn[EE];
__device__ __align__(16) float         g_enorm[EE];
__device__ __align__(16) int           g_pos[EE];
__device__ __align__(16) int           g_degcnt[NN];
__device__ __align__(16) int           g_indeg[NN];
__device__ __align__(16) int           g_cursor[NN];
__device__ __align__(16) int           g_off[NN + 1];
__device__ __align__(16) int           g_bsum[128];
__device__ __align__(16) float         g_invdeg[NN];
__device__ __align__(16) float         g_dinv[NN];
__device__ __align__(16) float         g_scl[LL * DD];
__device__ __align__(16) float         g_sft[LL * DD];
__device__ int g_is64;

__device__ __forceinline__ void split4(float v0, float v1, float v2, float v3,
                                       uint2& hi, uint2& lo) {
    __nv_bfloat162 p0 = __floats2bfloat162_rn(v0, v1);
    __nv_bfloat162 p1 = __floats2bfloat162_rn(v2, v3);
    float2 f0 = __bfloat1622float2(p0);
    float2 f1 = __bfloat1622float2(p1);
    __nv_bfloat162 q0 = __floats2bfloat162_rn(v0 - f0.x, v1 - f0.y);
    __nv_bfloat162 q1 = __floats2bfloat162_rn(v2 - f1.x, v3 - f1.y);
    hi = make_uint2(*(uint32_t*)&p0, *(uint32_t*)&p1);
    lo = make_uint2(*(uint32_t*)&q0, *(uint32_t*)&q1);
}

// ---------------------------------------------------------------------------
// Preprocessing
// ---------------------------------------------------------------------------
__global__ void k_detect(const int* __restrict__ ei32) {
    __shared__ int s_any;
    if (threadIdx.x == 0) s_any = 0;
    __syncthreads();
    int v = 0;
    for (int i = threadIdx.x; i < 4096; i += blockDim.x)
        v |= ei32[2 * i + 1];
    atomicOr(&s_any, v);
    __syncthreads();
    if (threadIdx.x == 0) g_is64 = (s_any == 0) ? 1 : 0;
}

__global__ void k_zero() {
    int i = blockIdx.x * blockDim.x + threadIdx.x;
    if (i < NN) { g_degcnt[i] = 0; g_indeg[i] = 0; g_cursor[i] = 0; }
}

__device__ __forceinline__ void load_edge(const void* ei, int e, int& r, int& c) {
    if (g_is64) {
        const long long* p = (const long long*)ei;
        r = (int)p[e]; c = (int)p[EE + e];
    } else {
        const int* p = (const int*)ei;
        r = p[e]; c = p[EE + e];
    }
    r = min(max(r, 0), NN - 1);
    c = min(max(c, 0), NN - 1);
}

__global__ void k_edge_pre(const void* __restrict__ ei) {
    int e = blockIdx.x * blockDim.x + threadIdx.x;
    if (e >= EE) return;
    int r, c; load_edge(ei, e, r, c);
    atomicAdd(&g_degcnt[r], 1);
    atomicAdd(&g_indeg[c], 1);
}

__global__ void k_node() {
    int n = blockIdx.x * blockDim.x + threadIdx.x;
    if (n >= NN) return;
    float d = (float)(g_degcnt[n] + 1);
    g_invdeg[n] = 1.0f / d;
    g_dinv[n]   = rsqrtf(d);
}

__global__ void k_scan1() {            // grid 98, block 1024
    __shared__ int s[1024];
    int i = blockIdx.x * 1024 + threadIdx.x;
    int v = (i < NN) ? g_indeg[i] : 0;
    s[threadIdx.x] = v;
    __syncthreads();
    for (int d = 1; d < 1024; d <<= 1) {
        int t = (threadIdx.x >= d) ? s[threadIdx.x - d] : 0;
        __syncthreads();
        s[threadIdx.x] += t;
        __syncthreads();
    }
    if (i < NN) g_off[i] = s[threadIdx.x] - v;
    if (threadIdx.x == 1023) g_bsum[blockIdx.x] = s[1023];
}

__global__ void k_scan2() {            // 1 block, 128 threads
    __shared__ int s[128];
    int t = threadIdx.x;
    s[t] = (t < 98) ? g_bsum[t] : 0;
    __syncthreads();
    for (int d = 1; d < 128; d <<= 1) {
        int v = (t >= d) ? s[t - d] : 0;
        __syncthreads();
        s[t] += v;
        __syncthreads();
    }
    if (t < 98) g_bsum[t] = s[t];
}

__global__ void k_scan3() {            // grid 98, block 1024
    int i = blockIdx.x * 1024 + threadIdx.x;
    int add = (blockIdx.x > 0) ? g_bsum[blockIdx.x - 1] : 0;
    if (i < NN) g_off[i] += add;
    if (i == NN) g_off[NN] = EE;
}

__global__ void k_place(const void* __restrict__ ei) {
    int e = blockIdx.x * blockDim.x + threadIdx.x;
    if (e >= EE) return;
    int r, c; load_edge(ei, e, r, c);
    int pos = g_off[c] + atomicAdd(&g_cursor[c], 1);
    g_srcn[pos]  = r;
    g_enorm[pos] = g_dinv[r] * g_dinv[c];
    g_pos[e]     = pos;
}

__global__ void k_pack2(const int4* __restrict__ ea) {
    int i = blockIdx.x * blockDim.x + threadIdx.x;
    if (i >= EE * 8) return;
    int e = i >> 3, g = i & 7;
    const int4* p = ea + (size_t)e * 32 + g * 4;
    unsigned int u = 0;
    #pragma unroll
    for (int q = 0; q < 4; q++) {
        int4 v = __ldg(&p[q]);
        u |= ((unsigned)v.x & 3u) << (q * 8 + 0);
        u |= ((unsigned)v.y & 3u) << (q * 8 + 2);
        u |= ((unsigned)v.z & 3u) << (q * 8 + 4);
        u |= ((unsigned)v.w & 3u) << (q * 8 + 6);
    }
    ((unsigned int*)g_ea)[(size_t)g_pos[e] * 8 + g] = u;
}

__global__ void k_bnconst(const float* __restrict__ gamma, const float* __restrict__ beta,
                          const float* __restrict__ mean,  const float* __restrict__ var) {
    int i = blockIdx.x * blockDim.x + threadIdx.x;
    if (i >= LL * DD) return;
    float s = gamma[i] * rsqrtf(var[i] + BN_EPS);
    g_scl[i] = s;
    g_sft[i] = beta[i] - mean[i] * s;
}

// ---------------------------------------------------------------------------
// Tensor-core GEMM, bf16 hi/lo 3-term, 512 threads, DUAL accumulator chains:
//   acc_hh <- ah*bh   and   acc_ml <- ah*bl + al*bh   (independent), summed
//   element-wise at store. Halves the per-tile HMMA dependency chain.
// ---------------------------------------------------------------------------
__global__ __launch_bounds__(512, 1)
void k_gemm_tc(const float* __restrict__ A_in, const float* __restrict__ W, int aff)
{
    extern __shared__ __nv_bfloat16 sm[];
    __nv_bfloat16* sWh = sm;                       // [128][SROW]
    __nv_bfloat16* sWl = sm + 128 * SROW;
    __nv_bfloat16* sAb = sm + 2 * 128 * SROW;      // [2 bufs][hi/lo][128][SROW]
    __shared__ float sScl[DD], sSft[DD];

    const float* A = A_in ? A_in : g_hn;
    int tid = threadIdx.x;
    bool doaff = (aff >= 0);

    if (tid < DD) {
        sScl[tid] = doaff ? g_scl[aff + tid] : 1.0f;
        sSft[tid] = doaff ? g_sft[aff + tid] : 0.0f;
    }

    for (int idx = tid; idx < 128 * 32; idx += 512) {
        int row = idx >> 5, c0 = (idx & 31) << 2;
        float4 w = __ldg((const float4*)(W + row * DD + c0));
        uint2 hi, lo;
        split4(w.x, w.y, w.z, w.w, hi, lo);
        *(uint2*)(sWh + row * SROW + c0) = hi;
        *(uint2*)(sWl + row * SROW + c0) = lo;
    }

    int wid = tid >> 5;
    int wm  = wid & 7;             // m-chunk (16 rows)
    int wn  = wid >> 3;            // n-half (64 cols)
    int r   = tid >> 2;            // staging row 0..127
    int ch  = (tid & 3) << 3;      // float4 col offset: 0,8,16,24

    int t = blockIdx.x;
    float4 st[8];
    if (t < NT) {
        int grow = min(t * 128 + r, NN - 1);
        const float4* src = (const float4*)(A + (size_t)grow * DD) + ch;
        #pragma unroll
        for (int i = 0; i < 8; i++) st[i] = __ldg(&src[i]);
    }
    __syncthreads();

    int buf = 0;
    while (t < NT) {
        __nv_bfloat16* sAh = sAb + buf * 2 * 128 * SROW;
        __nv_bfloat16* sAl = sAh + 128 * SROW;
        #pragma unroll
        for (int i = 0; i < 8; i++) {
            int c = (ch + i) * 4;
            float v0 = st[i].x, v1 = st[i].y, v2 = st[i].z, v3 = st[i].w;
            if (doaff) {
                v0 = fmaxf(fmaf(v0, sScl[c + 0], sSft[c + 0]), 0.f);
                v1 = fmaxf(fmaf(v1, sScl[c + 1], sSft[c + 1]), 0.f);
                v2 = fmaxf(fmaf(v2, sScl[c + 2], sSft[c + 2]), 0.f);
                v3 = fmaxf(fmaf(v3, sScl[c + 3], sSft[c + 3]), 0.f);
            }
            uint2 hi, lo;
            split4(v0, v1, v2, v3, hi, lo);
            *(uint2*)(sAh + r * SROW + c) = hi;
            *(uint2*)(sAl + r * SROW + c) = lo;
        }
        __syncthreads();

        int tn = t + GEMM_GRID;
        if (tn < NT) {
            int grow = min(tn * 128 + r, NN - 1);
            const float4* src = (const float4*)(A + (size_t)grow * DD) + ch;
            #pragma unroll
            for (int i = 0; i < 8; i++) st[i] = __ldg(&src[i]);
        }

        int m0 = wm * 16;
        wmma::fragment<wmma::matrix_a, 16, 16, 16, __nv_bfloat16, wmma::row_major> fah[8];
        #pragma unroll
        for (int k = 0; k < 8; k++)
            wmma::load_matrix_sync(fah[k], sAh + m0 * SROW + k * 16, SROW);

        float* outbase = g_hl + (size_t)(t * 128 + m0) * DD + wn * 64;
        #pragma unroll
        for (int nn = 0; nn < 4; nn++) {
            int c0 = wn * 64 + nn * 16;
            wmma::fragment<wmma::accumulator, 16, 16, 16, float> acc_hh, acc_ml;
            wmma::fill_fragment(acc_hh, 0.f);
            wmma::fill_fragment(acc_ml, 0.f);
            #pragma unroll
            for (int k = 0; k < 8; k++) {
                wmma::fragment<wmma::matrix_b, 16, 16, 16, __nv_bfloat16, wmma::col_major> fbh, fbl;
                wmma::fragment<wmma::matrix_a, 16, 16, 16, __nv_bfloat16, wmma::row_major> falk;
                wmma::load_matrix_sync(fbh, sWh + c0 * SROW + k * 16, SROW);
                wmma::load_matrix_sync(fbl, sWl + c0 * SROW + k * 16, SROW);
                wmma::load_matrix_sync(falk, sAl + m0 * SROW + k * 16, SROW);
                wmma::mma_sync(acc_hh, fah[k], fbh, acc_hh);   // chain 1
                wmma::mma_sync(acc_ml, fah[k], fbl, acc_ml);   // chain 2
                wmma::mma_sync(acc_ml, falk, fbh, acc_ml);     // chain 2
            }
            #pragma unroll
            for (int q = 0; q < acc_hh.num_elements; q++)
                acc_hh.x[q] += acc_ml.x[q];
            wmma::store_matrix_sync(outbase + nn * 16, acc_hh, DD, wmma::mem_row_major);
        }
        buf ^= 1;
        t = tn;
    }
}

// ---------------------------------------------------------------------------
// CSR aggregation (unchanged from R13)
// ---------------------------------------------------------------------------
__device__ __forceinline__ void acc_edge2(float4& acc, float4 h, unsigned int a,
                                          float nrm, float4 b4) {
    acc.x += fmaxf(h.x + b4.x + (float)( a       & 3u), 0.f) * nrm;
    acc.y += fmaxf(h.y + b4.y + (float)((a >> 2) & 3u), 0.f) * nrm;
    acc.z += fmaxf(h.z + b4.z + (float)((a >> 4) & 3u), 0.f) * nrm;
    acc.w += fmaxf(h.w + b4.w + (float)((a >> 6) & 3u), 0.f) * nrm;
}

__device__ __forceinline__ void drain_edges(int j, int end, int lane,
                                            float4& acc, float4 b4,
                                            const float4* hl4) {
    for (; j + 1 < end; j += 2) {
        int   s0 = __ldg(&g_srcn[j]);
        int   s1 = __ldg(&g_srcn[j + 1]);
        float n0 = __ldg(&g_enorm[j]);
        float n1 = __ldg(&g_enorm[j + 1]);
        unsigned int a0 = __ldg(&g_ea[(size_t)j * 32 + lane]);
        unsigned int a1 = __ldg(&g_ea[(size_t)(j + 1) * 32 + lane]);
        float4 h0 = __ldg(hl4 + (size_t)s0 * 32 + lane);
        float4 h1 = __ldg(hl4 + (size_t)s1 * 32 + lane);
        acc_edge2(acc, h0, a0, n0, b4);
        acc_edge2(acc, h1, a1, n1, b4);
    }
    if (j < end) {
        int   s0 = __ldg(&g_srcn[j]);
        float n0 = __ldg(&g_enorm[j]);
        unsigned int a0 = __ldg(&g_ea[(size_t)j * 32 + lane]);
        float4 h0 = __ldg(hl4 + (size_t)s0 * 32 + lane);
        acc_edge2(acc, h0, a0, n0, b4);
    }
}

__device__ __forceinline__ void finish_node(int n, int lane, float4 acc,
                                            float4 b4, float4 rt,
                                            float4 sc, float4 sf, int bnoff,
                                            const float4* hl4,
                                            float* __restrict__ outp) {
    float4 hs = __ldg(hl4 + (size_t)n * 32 + lane);
    float  id = __ldg(&g_invdeg[n]);
    acc.x += fmaxf(hs.x + b4.x + rt.x, 0.f) * id;
    acc.y += fmaxf(hs.y + b4.y + rt.y, 0.f) * id;
    acc.z += fmaxf(hs.z + b4.z + rt.z, 0.f) * id;
    acc.w += fmaxf(hs.w + b4.w + rt.w, 0.f) * id;
    if (bnoff >= 0) {
        acc.x = fmaf(acc.x, sc.x, sf.x);
        acc.y = fmaf(acc.y, sc.y, sf.y);
        acc.z = fmaf(acc.z, sc.z, sf.z);
        acc.w = fmaf(acc.w, sc.w, sf.w);
        ((float4*)outp)[(size_t)n * 32 + lane] = acc;
    } else {
        ((float4*)g_hn)[(size_t)n * 32 + lane] = acc;
    }
}

__global__ __launch_bounds__(256)
void k_edge_csr(const float* __restrict__ bias, const float* __restrict__ root,
                float* __restrict__ outp, int bnoff)
{
    int gw   = (blockIdx.x * blockDim.x + threadIdx.x) >> 5;
    int lane = threadIdx.x & 31;
    const int nwarps = EDGE_BLOCKS * 8;

    const float4* hl4 = (const float4*)g_hl;
    float4 b4 = __ldg((const float4*)bias + lane);
    float4 rt = __ldg((const float4*)root + lane);
    float4 sc = make_float4(0,0,0,0), sf = make_float4(0,0,0,0);
    if (bnoff >= 0) {
        sc = *(const float4*)&g_scl[bnoff + lane * 4];
        sf = *(const float4*)&g_sft[bnoff + lane * 4];
    }

    for (int n0 = gw; n0 < NN; n0 += 2 * nwarps) {
        int n1 = n0 + nwarps;
        bool has1 = (n1 < NN);

        int beg0 = __ldg(&g_off[n0]);
        int end0 = __ldg(&g_off[n0 + 1]);
        int beg1 = 0, end1 = 0;
        if (has1) { beg1 = __ldg(&g_off[n1]); end1 = __ldg(&g_off[n1 + 1]); }

        float4 acc0 = make_float4(0.f, 0.f, 0.f, 0.f);
        float4 acc1 = make_float4(0.f, 0.f, 0.f, 0.f);

        int j0 = beg0, j1 = beg1;
        while (j0 + 1 < end0 && j1 + 1 < end1) {
            int   sa = __ldg(&g_srcn[j0]);
            int   sb = __ldg(&g_srcn[j0 + 1]);
            int   sx = __ldg(&g_srcn[j1]);
            int   sy = __ldg(&g_srcn[j1 + 1]);
            float na = __ldg(&g_enorm[j0]);
            float nb = __ldg(&g_enorm[j0 + 1]);
            float nx = __ldg(&g_enorm[j1]);
            float ny = __ldg(&g_enorm[j1 + 1]);
            unsigned int aa = __ldg(&g_ea[(size_t)j0 * 32 + lane]);
            unsigned int ab = __ldg(&g_ea[(size_t)(j0 + 1) * 32 + lane]);
            unsigned int ax = __ldg(&g_ea[(size_t)j1 * 32 + lane]);
            unsigned int ay = __ldg(&g_ea[(size_t)(j1 + 1) * 32 + lane]);
            float4 ha = __ldg(hl4 + (size_t)sa * 32 + lane);
            float4 hb = __ldg(hl4 + (size_t)sb * 32 + lane);
            float4 hx = __ldg(hl4 + (size_t)sx * 32 + lane);
            float4 hy = __ldg(hl4 + (size_t)sy * 32 + lane);
            acc_edge2(acc0, ha, aa, na, b4);
            acc_edge2(acc0, hb, ab, nb, b4);
            acc_edge2(acc1, hx, ax, nx, b4);
            acc_edge2(acc1, hy, ay, ny, b4);
            j0 += 2; j1 += 2;
        }
        drain_edges(j0, end0, lane, acc0, b4, hl4);
        finish_node(n0, lane, acc0, b4, rt, sc, sf, bnoff, hl4, outp);
        if (has1) {
            drain_edges(j1, end1, lane, acc1, b4, hl4);
            finish_node(n1, lane, acc1, b4, rt, sc, sf, bnoff, hl4, outp);
        }
    }
}

// ---------------------------------------------------------------------------
// Host driver (graph-capturable, natural order)
// ---------------------------------------------------------------------------
extern "C" void kernel_launch(void* const* d_in, const int* in_sizes, int n_in,
                              void* d_out, int out_size)
{
    const float* x     = (const float*)d_in[0];
    const void*  ei    = d_in[1];
    const int*   ea    = (const int*)d_in[2];
    const float* W     = (const float*)d_in[3];
    const float* b     = (const float*)d_in[4];
    const float* root  = (const float*)d_in[5];
    const float* gamma = (const float*)d_in[6];
    const float* beta  = (const float*)d_in[7];
    const float* mean  = (const float*)d_in[8];
    const float* var   = (const float*)d_in[9];
    (void)in_sizes; (void)n_in; (void)out_size;

    const int smem_bytes = (2 + 4) * 128 * SROW * (int)sizeof(__nv_bfloat16); // 208896
    cudaFuncSetAttribute(k_gemm_tc, cudaFuncAttributeMaxDynamicSharedMemorySize, smem_bytes);

    k_detect<<<1, 256>>>((const int*)ei);
    k_zero<<<(NN + 255) / 256, 256>>>();
    k_edge_pre<<<(EE + 255) / 256, 256>>>(ei);
    k_node<<<(NN + 255) / 256, 256>>>();
    k_scan1<<<98, 1024>>>();
    k_scan2<<<1, 128>>>();
    k_scan3<<<98, 1024>>>();
    k_place<<<(EE + 255) / 256, 256>>>(ei);
    k_pack2<<<(EE * 8 + 255) / 256, 256>>>((const int4*)ea);
    k_bnconst<<<(LL * DD + 255) / 256, 256>>>(gamma, beta, mean, var);

    for (int l = 0; l < LL; ++l) {
        const float* A   = (l == 0) ? x : nullptr;
        int          aff = (l == 0) ? -1 : (l - 1) * DD;
        k_gemm_tc<<<GEMM_GRID, 512, smem_bytes>>>(A, W + (size_t)l * DD * DD, aff);
        float* outp = (l == LL - 1) ? (float*)d_out : nullptr;
        int    bn   = (l == LL - 1) ? (LL - 1) * DD : -1;
        k_edge_csr<<<EDGE_BLOCKS, 256>>>(b + (size_t)l * DD, root + (size_t)l * DD, outp, bn);
    }
}

// round 15
// speedup vs baseline: 1.1800x; 1.1091x over previous
#include <cuda_runtime.h>
#include <cuda_bf16.h>
#include <mma.h>
#include <cstdint>
#include <cstddef>

using namespace nvcuda;

#define NN 100000
#define EE 600000
#define DD 128
#define LL 5
#define BN_EPS 1e-5f
#define NT 782
#define NPAD (NT * 128)
#define SROW 136
#define EDGE_BLOCKS 592

// ---------------------------------------------------------------------------
// Device scratch
// ---------------------------------------------------------------------------
__device__ __align__(16) float         g_hl[(size_t)NPAD * DD];   // GEMM out (fp32)
__device__ __align__(16) __nv_bfloat16 g_Ah[(size_t)NPAD * DD];   // GEMM in, hi plane
__device__ __align__(16) __nv_bfloat16 g_Al[(size_t)NPAD * DD];   // GEMM in, lo plane
__device__ __align__(16) unsigned char g_ea[(size_t)EE * 32];     // 2-bit attr, CSR
__device__ __align__(16) int           g_srcn[EE];
__device__ __align__(16) float         g_enorm[EE];
__device__ __align__(16) int           g_pos[EE];
__device__ __align__(16) int           g_degcnt[NN];
__device__ __align__(16) int           g_indeg[NN];
__device__ __align__(16) int           g_cursor[NN];
__device__ __align__(16) int           g_off[NN + 1];
__device__ __align__(16) int           g_bsum[128];
__device__ __align__(16) float         g_invdeg[NN];
__device__ __align__(16) float         g_dinv[NN];
__device__ __align__(16) float         g_scl[LL * DD];
__device__ __align__(16) float         g_sft[LL * DD];
__device__ int g_is64;

__device__ __forceinline__ void split4(float v0, float v1, float v2, float v3,
                                       uint2& hi, uint2& lo) {
    __nv_bfloat162 p0 = __floats2bfloat162_rn(v0, v1);
    __nv_bfloat162 p1 = __floats2bfloat162_rn(v2, v3);
    float2 f0 = __bfloat1622float2(p0);
    float2 f1 = __bfloat1622float2(p1);
    __nv_bfloat162 q0 = __floats2bfloat162_rn(v0 - f0.x, v1 - f0.y);
    __nv_bfloat162 q1 = __floats2bfloat162_rn(v2 - f1.x, v3 - f1.y);
    hi = make_uint2(*(uint32_t*)&p0, *(uint32_t*)&p1);
    lo = make_uint2(*(uint32_t*)&q0, *(uint32_t*)&q1);
}

// ---------------------------------------------------------------------------
// Preprocessing
// ---------------------------------------------------------------------------
__global__ void k_detect(const int* __restrict__ ei32) {
    __shared__ int s_any;
    if (threadIdx.x == 0) s_any = 0;
    __syncthreads();
    int v = 0;
    for (int i = threadIdx.x; i < 4096; i += blockDim.x)
        v |= ei32[2 * i + 1];
    atomicOr(&s_any, v);
    __syncthreads();
    if (threadIdx.x == 0) g_is64 = (s_any == 0) ? 1 : 0;
}

__global__ void k_zero() {
    int i = blockIdx.x * blockDim.x + threadIdx.x;
    if (i < NN) { g_degcnt[i] = 0; g_indeg[i] = 0; g_cursor[i] = 0; }
}

__device__ __forceinline__ void load_edge(const void* ei, int e, int& r, int& c) {
    if (g_is64) {
        const long long* p = (const long long*)ei;
        r = (int)p[e]; c = (int)p[EE + e];
    } else {
        const int* p = (const int*)ei;
        r = p[e]; c = p[EE + e];
    }
    r = min(max(r, 0), NN - 1);
    c = min(max(c, 0), NN - 1);
}

__global__ void k_edge_pre(const void* __restrict__ ei) {
    int e = blockIdx.x * blockDim.x + threadIdx.x;
    if (e >= EE) return;
    int r, c; load_edge(ei, e, r, c);
    atomicAdd(&g_degcnt[r], 1);
    atomicAdd(&g_indeg[c], 1);
}

__global__ void k_node() {
    int n = blockIdx.x * blockDim.x + threadIdx.x;
    if (n >= NN) return;
    float d = (float)(g_degcnt[n] + 1);
    g_invdeg[n] = 1.0f / d;
    g_dinv[n]   = rsqrtf(d);
}

__global__ void k_scan1() {            // grid 98, block 1024
    __shared__ int s[1024];
    int i = blockIdx.x * 1024 + threadIdx.x;
    int v = (i < NN) ? g_indeg[i] : 0;
    s[threadIdx.x] = v;
    __syncthreads();
    for (int d = 1; d < 1024; d <<= 1) {
        int t = (threadIdx.x >= d) ? s[threadIdx.x - d] : 0;
        __syncthreads();
        s[threadIdx.x] += t;
        __syncthreads();
    }
    if (i < NN) g_off[i] = s[threadIdx.x] - v;
    if (threadIdx.x == 1023) g_bsum[blockIdx.x] = s[1023];
}

__global__ void k_scan2() {            // 1 block, 128 threads
    __shared__ int s[128];
    int t = threadIdx.x;
    s[t] = (t < 98) ? g_bsum[t] : 0;
    __syncthreads();
    for (int d = 1; d < 128; d <<= 1) {
        int v = (t >= d) ? s[t - d] : 0;
        __syncthreads();
        s[t] += v;
        __syncthreads();
    }
    if (t < 98) g_bsum[t] = s[t];
}

__global__ void k_scan3() {            // grid 98, block 1024
    int i = blockIdx.x * 1024 + threadIdx.x;
    int add = (blockIdx.x > 0) ? g_bsum[blockIdx.x - 1] : 0;
    if (i < NN) g_off[i] += add;
    if (i == NN) g_off[NN] = EE;
}

__global__ void k_place(const void* __restrict__ ei) {
    int e = blockIdx.x * blockDim.x + threadIdx.x;
    if (e >= EE) return;
    int r, c; load_edge(ei, e, r, c);
    int pos = g_off[c] + atomicAdd(&g_cursor[c], 1);
    g_srcn[pos]  = r;
    g_enorm[pos] = g_dinv[r] * g_dinv[c];
    g_pos[e]     = pos;
}

__global__ void k_pack2(const int4* __restrict__ ea) {
    int i = blockIdx.x * blockDim.x + threadIdx.x;
    if (i >= EE * 8) return;
    int e = i >> 3, g = i & 7;
    const int4* p = ea + (size_t)e * 32 + g * 4;
    unsigned int u = 0;
    #pragma unroll
    for (int q = 0; q < 4; q++) {
        int4 v = __ldg(&p[q]);
        u |= ((unsigned)v.x & 3u) << (q * 8 + 0);
        u |= ((unsigned)v.y & 3u) << (q * 8 + 2);
        u |= ((unsigned)v.z & 3u) << (q * 8 + 4);
        u |= ((unsigned)v.w & 3u) << (q * 8 + 6);
    }
    ((unsigned int*)g_ea)[(size_t)g_pos[e] * 8 + g] = u;
}

__global__ void k_bnconst(const float* __restrict__ gamma, const float* __restrict__ beta,
                          const float* __restrict__ mean,  const float* __restrict__ var) {
    int i = blockIdx.x * blockDim.x + threadIdx.x;
    if (i >= LL * DD) return;
    float s = gamma[i] * rsqrtf(var[i] + BN_EPS);
    g_scl[i] = s;
    g_sft[i] = beta[i] - mean[i] * s;
}

// Convert x (fp32) -> bf16 hi/lo planes (layer-0 GEMM input)
__global__ void k_xconv(const float4* __restrict__ x) {
    int i = blockIdx.x * blockDim.x + threadIdx.x;   // float4 index
    if (i >= NN * 32) return;
    float4 v = __ldg(&x[i]);
    uint2 hi, lo;
    split4(v.x, v.y, v.z, v.w, hi, lo);
    ((uint2*)g_Ah)[i] = hi;
    ((uint2*)g_Al)[i] = lo;
}

// ---------------------------------------------------------------------------
// Tensor-core GEMM: g_hl = A @ W^T, A read as bf16 hi/lo planes DIRECTLY from
// global (no A smem, no staging, no per-tile sync). W hi/lo resident in smem.
// Grid NT, 256 threads (8 warps); warp = 16 rows x 128 cols, dual acc chains.
// ---------------------------------------------------------------------------
__global__ __launch_bounds__(256)
void k_gemm_tc(const float* __restrict__ W)
{
    extern __shared__ __nv_bfloat16 sm[];
    __nv_bfloat16* sWh = sm;                  // [128][SROW]
    __nv_bfloat16* sWl = sm + 128 * SROW;

    int tid = threadIdx.x;

    for (int idx = tid; idx < 128 * 32; idx += 256) {
        int row = idx >> 5, c0 = (idx & 31) << 2;
        float4 w = __ldg((const float4*)(W + row * DD + c0));
        uint2 hi, lo;
        split4(w.x, w.y, w.z, w.w, hi, lo);
        *(uint2*)(sWh + row * SROW + c0) = hi;
        *(uint2*)(sWl + row * SROW + c0) = lo;
    }
    __syncthreads();

    int wid = tid >> 5;
    int row0 = blockIdx.x * 128 + wid * 16;

    wmma::fragment<wmma::matrix_a, 16, 16, 16, __nv_bfloat16, wmma::row_major> fah[8], fal[8];
    #pragma unroll
    for (int k = 0; k < 8; k++) {
        wmma::load_matrix_sync(fah[k], g_Ah + (size_t)row0 * DD + k * 16, DD);
        wmma::load_matrix_sync(fal[k], g_Al + (size_t)row0 * DD + k * 16, DD);
    }

    float* outbase = g_hl + (size_t)row0 * DD;
    #pragma unroll
    for (int nn = 0; nn < 8; nn++) {
        wmma::fragment<wmma::accumulator, 16, 16, 16, float> acc_hh, acc_ml;
        wmma::fill_fragment(acc_hh, 0.f);
        wmma::fill_fragment(acc_ml, 0.f);
        #pragma unroll
        for (int k = 0; k < 8; k++) {
            wmma::fragment<wmma::matrix_b, 16, 16, 16, __nv_bfloat16, wmma::col_major> fbh, fbl;
            wmma::load_matrix_sync(fbh, sWh + (nn * 16) * SROW + k * 16, SROW);
            wmma::load_matrix_sync(fbl, sWl + (nn * 16) * SROW + k * 16, SROW);
            wmma::mma_sync(acc_hh, fah[k], fbh, acc_hh);
            wmma::mma_sync(acc_ml, fah[k], fbl, acc_ml);
            wmma::mma_sync(acc_ml, fal[k], fbh, acc_ml);
        }
        #pragma unroll
        for (int q = 0; q < acc_hh.num_elements; q++)
            acc_hh.x[q] += acc_ml.x[q];
        wmma::store_matrix_sync(outbase + nn * 16, acc_hh, DD, wmma::mem_row_major);
    }
}

// ---------------------------------------------------------------------------
// CSR aggregation: gathers fp32 g_hl; epilogue applies THIS layer's BN
// (+relu for l<L-1) and writes bf16 hi/lo planes (next GEMM input), or
// final BN -> fp32 out for the last layer (outp != nullptr).
// ---------------------------------------------------------------------------
__device__ __forceinline__ void acc_edge2(float4& acc, float4 h, unsigned int a,
                                          float nrm, float4 b4) {
    acc.x += fmaxf(h.x + b4.x + (float)( a       & 3u), 0.f) * nrm;
    acc.y += fmaxf(h.y + b4.y + (float)((a >> 2) & 3u), 0.f) * nrm;
    acc.z += fmaxf(h.z + b4.z + (float)((a >> 4) & 3u), 0.f) * nrm;
    acc.w += fmaxf(h.w + b4.w + (float)((a >> 6) & 3u), 0.f) * nrm;
}

__device__ __forceinline__ void drain_edges(int j, int end, int lane,
                                            float4& acc, float4 b4,
                                            const float4* hl4) {
    for (; j + 1 < end; j += 2) {
        int   s0 = __ldg(&g_srcn[j]);
        int   s1 = __ldg(&g_srcn[j + 1]);
        float n0 = __ldg(&g_enorm[j]);
        float n1 = __ldg(&g_enorm[j + 1]);
        unsigned int a0 = __ldg(&g_ea[(size_t)j * 32 + lane]);
        unsigned int a1 = __ldg(&g_ea[(size_t)(j + 1) * 32 + lane]);
        float4 h0 = __ldg(hl4 + (size_t)s0 * 32 + lane);
        float4 h1 = __ldg(hl4 + (size_t)s1 * 32 + lane);
        acc_edge2(acc, h0, a0, n0, b4);
        acc_edge2(acc, h1, a1, n1, b4);
    }
    if (j < end) {
        int   s0 = __ldg(&g_srcn[j]);
        float n0 = __ldg(&g_enorm[j]);
        unsigned int a0 = __ldg(&g_ea[(size_t)j * 32 + lane]);
        float4 h0 = __ldg(hl4 + (size_t)s0 * 32 + lane);
        acc_edge2(acc, h0, a0, n0, b4);
    }
}

__device__ __forceinline__ void finish_node(int n, int lane, float4 acc,
                                            float4 b4, float4 rt,
                                            float4 sc, float4 sf,
                                            const float4* hl4,
                                            float* __restrict__ outp) {
    float4 hs = __ldg(hl4 + (size_t)n * 32 + lane);
    float  id = __ldg(&g_invdeg[n]);
    acc.x += fmaxf(hs.x + b4.x + rt.x, 0.f) * id;
    acc.y += fmaxf(hs.y + b4.y + rt.y, 0.f) * id;
    acc.z += fmaxf(hs.z + b4.z + rt.z, 0.f) * id;
    acc.w += fmaxf(hs.w + b4.w + rt.w, 0.f) * id;
    // BN of this layer
    acc.x = fmaf(acc.x, sc.x, sf.x);
    acc.y = fmaf(acc.y, sc.y, sf.y);
    acc.z = fmaf(acc.z, sc.z, sf.z);
    acc.w = fmaf(acc.w, sc.w, sf.w);
    if (outp) {                       // last layer: no relu, fp32 out
        ((float4*)outp)[(size_t)n * 32 + lane] = acc;
    } else {                          // relu + bf16 hi/lo planes
        acc.x = fmaxf(acc.x, 0.f);
        acc.y = fmaxf(acc.y, 0.f);
        acc.z = fmaxf(acc.z, 0.f);
        acc.w = fmaxf(acc.w, 0.f);
        uint2 hi, lo;
        split4(acc.x, acc.y, acc.z, acc.w, hi, lo);
        ((uint2*)g_Ah)[(size_t)n * 32 + lane] = hi;
        ((uint2*)g_Al)[(size_t)n * 32 + lane] = lo;
    }
}

__global__ __launch_bounds__(256)
void k_edge_csr(const float* __restrict__ bias, const float* __restrict__ root,
                float* __restrict__ outp, int bnoff)
{
    int gw   = (blockIdx.x * blockDim.x + threadIdx.x) >> 5;
    int lane = threadIdx.x & 31;
    const int nwarps = EDGE_BLOCKS * 8;

    const float4* hl4 = (const float4*)g_hl;
    float4 b4 = __ldg((const float4*)bias + lane);
    float4 rt = __ldg((const float4*)root + lane);
    float4 sc = *(const float4*)&g_scl[bnoff + lane * 4];
    float4 sf = *(const float4*)&g_sft[bnoff + lane * 4];

    for (int n0 = gw; n0 < NN; n0 += 2 * nwarps) {
        int n1 = n0 + nwarps;
        bool has1 = (n1 < NN);

        int beg0 = __ldg(&g_off[n0]);
        int end0 = __ldg(&g_off[n0 + 1]);
        int beg1 = 0, end1 = 0;
        if (has1) { beg1 = __ldg(&g_off[n1]); end1 = __ldg(&g_off[n1 + 1]); }

        float4 acc0 = make_float4(0.f, 0.f, 0.f, 0.f);
        float4 acc1 = make_float4(0.f, 0.f, 0.f, 0.f);

        int j0 = beg0, j1 = beg1;
        while (j0 + 1 < end0 && j1 + 1 < end1) {
            int   sa = __ldg(&g_srcn[j0]);
            int   sb = __ldg(&g_srcn[j0 + 1]);
            int   sx = __ldg(&g_srcn[j1]);
            int   sy = __ldg(&g_srcn[j1 + 1]);
            float na = __ldg(&g_enorm[j0]);
            float nb = __ldg(&g_enorm[j0 + 1]);
            float nx = __ldg(&g_enorm[j1]);
            float ny = __ldg(&g_enorm[j1 + 1]);
            unsigned int aa = __ldg(&g_ea[(size_t)j0 * 32 + lane]);
            unsigned int ab = __ldg(&g_ea[(size_t)(j0 + 1) * 32 + lane]);
            unsigned int ax = __ldg(&g_ea[(size_t)j1 * 32 + lane]);
            unsigned int ay = __ldg(&g_ea[(size_t)(j1 + 1) * 32 + lane]);
            float4 ha = __ldg(hl4 + (size_t)sa * 32 + lane);
            float4 hb = __ldg(hl4 + (size_t)sb * 32 + lane);
            float4 hx = __ldg(hl4 + (size_t)sx * 32 + lane);
            float4 hy = __ldg(hl4 + (size_t)sy * 32 + lane);
            acc_edge2(acc0, ha, aa, na, b4);
            acc_edge2(acc0, hb, ab, nb, b4);
            acc_edge2(acc1, hx, ax, nx, b4);
            acc_edge2(acc1, hy, ay, ny, b4);
            j0 += 2; j1 += 2;
        }
        drain_edges(j0, end0, lane, acc0, b4, hl4);
        finish_node(n0, lane, acc0, b4, rt, sc, sf, hl4, outp);
        if (has1) {
            drain_edges(j1, end1, lane, acc1, b4, hl4);
            finish_node(n1, lane, acc1, b4, rt, sc, sf, hl4, outp);
        }
    }
}

// ---------------------------------------------------------------------------
// Host driver (graph-capturable)
// ---------------------------------------------------------------------------
extern "C" void kernel_launch(void* const* d_in, const int* in_sizes, int n_in,
                              void* d_out, int out_size)
{
    const float* x     = (const float*)d_in[0];
    const void*  ei    = d_in[1];
    const int*   ea    = (const int*)d_in[2];
    const float* W     = (const float*)d_in[3];
    const float* b     = (const float*)d_in[4];
    const float* root  = (const float*)d_in[5];
    const float* gamma = (const float*)d_in[6];
    const float* beta  = (const float*)d_in[7];
    const float* mean  = (const float*)d_in[8];
    const float* var   = (const float*)d_in[9];
    (void)in_sizes; (void)n_in; (void)out_size;

    const int smem_bytes = 2 * 128 * SROW * (int)sizeof(__nv_bfloat16); // 69632
    cudaFuncSetAttribute(k_gemm_tc, cudaFuncAttributeMaxDynamicSharedMemorySize, smem_bytes);

    k_detect<<<1, 256>>>((const int*)ei);
    k_zero<<<(NN + 255) / 256, 256>>>();
    k_edge_pre<<<(EE + 255) / 256, 256>>>(ei);
    k_node<<<(NN + 255) / 256, 256>>>();
    k_scan1<<<98, 1024>>>();
    k_scan2<<<1, 128>>>();
    k_scan3<<<98, 1024>>>();
    k_place<<<(EE + 255) / 256, 256>>>(ei);
    k_pack2<<<(EE * 8 + 255) / 256, 256>>>((const int4*)ea);
    k_bnconst<<<(LL * DD + 255) / 256, 256>>>(gamma, beta, mean, var);
    k_xconv<<<(NN * 32 + 255) / 256, 256>>>((const float4*)x);

    for (int l = 0; l < LL; ++l) {
        k_gemm_tc<<<NT, 256, smem_bytes>>>(W + (size_t)l * DD * DD);
        float* outp = (l == LL - 1) ? (float*)d_out : nullptr;
        k_edge_csr<<<EDGE_BLOCKS, 256>>>(b + (size_t)l * DD, root + (size_t)l * DD,
                                         outp, l * DD);
    }
}

// round 16
// speedup vs baseline: 1.2320x; 1.0441x over previous
#include <cuda_runtime.h>
#include <cuda_bf16.h>
#include <mma.h>
#include <cstdint>
#include <cstddef>

using namespace nvcuda;

#define NN 100000
#define EE 600000
#define DD 128
#define LL 5
#define BN_EPS 1e-5f
#define NT 782
#define NPAD (NT * 128)
#define SROW 136
#define EDGE_BLOCKS 592

// ---------------------------------------------------------------------------
// Device scratch
// ---------------------------------------------------------------------------
__device__ __align__(16) float         g_hl[(size_t)NPAD * DD];   // GEMM out (fp32)
__device__ __align__(16) __nv_bfloat16 g_Ah[(size_t)NPAD * DD];   // GEMM in, hi plane
__device__ __align__(16) __nv_bfloat16 g_Al[(size_t)NPAD * DD];   // GEMM in, lo plane
__device__ __align__(16) unsigned char g_ea[(size_t)EE * 32];     // 2-bit attr, CSR
__device__ __align__(16) int           g_srcn[EE];
__device__ __align__(16) float         g_enorm[EE];
__device__ __align__(16) int           g_pos[EE];
__device__ __align__(16) int           g_degcnt[NN];
__device__ __align__(16) int           g_indeg[NN];
__device__ __align__(16) int           g_cursor[NN];
__device__ __align__(16) int           g_off[NN + 1];
__device__ __align__(16) int           g_bsum[128];
__device__ __align__(16) float         g_invdeg[NN];
__device__ __align__(16) float         g_dinv[NN];
__device__ __align__(16) float         g_scl[LL * DD];
__device__ __align__(16) float         g_sft[LL * DD];
__device__ int g_is64;

__device__ __forceinline__ void split4(float v0, float v1, float v2, float v3,
                                       uint2& hi, uint2& lo) {
    __nv_bfloat162 p0 = __floats2bfloat162_rn(v0, v1);
    __nv_bfloat162 p1 = __floats2bfloat162_rn(v2, v3);
    float2 f0 = __bfloat1622float2(p0);
    float2 f1 = __bfloat1622float2(p1);
    __nv_bfloat162 q0 = __floats2bfloat162_rn(v0 - f0.x, v1 - f0.y);
    __nv_bfloat162 q1 = __floats2bfloat162_rn(v2 - f1.x, v3 - f1.y);
    hi = make_uint2(*(uint32_t*)&p0, *(uint32_t*)&p1);
    lo = make_uint2(*(uint32_t*)&q0, *(uint32_t*)&q1);
}

// ---------------------------------------------------------------------------
// Preprocessing
// ---------------------------------------------------------------------------
__global__ void k_detect(const int* __restrict__ ei32) {
    __shared__ int s_any;
    if (threadIdx.x == 0) s_any = 0;
    __syncthreads();
    int v = 0;
    for (int i = threadIdx.x; i < 4096; i += blockDim.x)
        v |= ei32[2 * i + 1];
    atomicOr(&s_any, v);
    __syncthreads();
    if (threadIdx.x == 0) g_is64 = (s_any == 0) ? 1 : 0;
}

__global__ void k_zero() {
    int i = blockIdx.x * blockDim.x + threadIdx.x;
    if (i < NN) { g_degcnt[i] = 0; g_indeg[i] = 0; g_cursor[i] = 0; }
}

__device__ __forceinline__ void load_edge(const void* ei, int e, int& r, int& c) {
    if (g_is64) {
        const long long* p = (const long long*)ei;
        r = (int)p[e]; c = (int)p[EE + e];
    } else {
        const int* p = (const int*)ei;
        r = p[e]; c = p[EE + e];
    }
    r = min(max(r, 0), NN - 1);
    c = min(max(c, 0), NN - 1);
}

__global__ void k_edge_pre(const void* __restrict__ ei) {
    int e = blockIdx.x * blockDim.x + threadIdx.x;
    if (e >= EE) return;
    int r, c; load_edge(ei, e, r, c);
    atomicAdd(&g_degcnt[r], 1);
    atomicAdd(&g_indeg[c], 1);
}

__global__ void k_node() {
    int n = blockIdx.x * blockDim.x + threadIdx.x;
    if (n >= NN) return;
    float d = (float)(g_degcnt[n] + 1);
    g_invdeg[n] = 1.0f / d;
    g_dinv[n]   = rsqrtf(d);
}

__global__ void k_scan1() {            // grid 98, block 1024
    __shared__ int s[1024];
    int i = blockIdx.x * 1024 + threadIdx.x;
    int v = (i < NN) ? g_indeg[i] : 0;
    s[threadIdx.x] = v;
    __syncthreads();
    for (int d = 1; d < 1024; d <<= 1) {
        int t = (threadIdx.x >= d) ? s[threadIdx.x - d] : 0;
        __syncthreads();
        s[threadIdx.x] += t;
        __syncthreads();
    }
    if (i < NN) g_off[i] = s[threadIdx.x] - v;
    if (threadIdx.x == 1023) g_bsum[blockIdx.x] = s[1023];
}

__global__ void k_scan2() {            // 1 block, 128 threads
    __shared__ int s[128];
    int t = threadIdx.x;
    s[t] = (t < 98) ? g_bsum[t] : 0;
    __syncthreads();
    for (int d = 1; d < 128; d <<= 1) {
        int v = (t >= d) ? s[t - d] : 0;
        __syncthreads();
        s[t] += v;
        __syncthreads();
    }
    if (t < 98) g_bsum[t] = s[t];
}

__global__ void k_scan3() {            // grid 98, block 1024
    int i = blockIdx.x * 1024 + threadIdx.x;
    int add = (blockIdx.x > 0) ? g_bsum[blockIdx.x - 1] : 0;
    if (i < NN) g_off[i] += add;
    if (i == NN) g_off[NN] = EE;
}

__global__ void k_place(const void* __restrict__ ei) {
    int e = blockIdx.x * blockDim.x + threadIdx.x;
    if (e >= EE) return;
    int r, c; load_edge(ei, e, r, c);
    int pos = g_off[c] + atomicAdd(&g_cursor[c], 1);
    g_srcn[pos]  = r;
    g_enorm[pos] = g_dinv[r] * g_dinv[c];
    g_pos[e]     = pos;
}

__global__ void k_pack2(const int4* __restrict__ ea) {
    int i = blockIdx.x * blockDim.x + threadIdx.x;
    if (i >= EE * 8) return;
    int e = i >> 3, g = i & 7;
    const int4* p = ea + (size_t)e * 32 + g * 4;
    unsigned int u = 0;
    #pragma unroll
    for (int q = 0; q < 4; q++) {
        int4 v = __ldg(&p[q]);
        u |= ((unsigned)v.x & 3u) << (q * 8 + 0);
        u |= ((unsigned)v.y & 3u) << (q * 8 + 2);
        u |= ((unsigned)v.z & 3u) << (q * 8 + 4);
        u |= ((unsigned)v.w & 3u) << (q * 8 + 6);
    }
    ((unsigned int*)g_ea)[(size_t)g_pos[e] * 8 + g] = u;
}

__global__ void k_bnconst(const float* __restrict__ gamma, const float* __restrict__ beta,
                          const float* __restrict__ mean,  const float* __restrict__ var) {
    int i = blockIdx.x * blockDim.x + threadIdx.x;
    if (i >= LL * DD) return;
    float s = gamma[i] * rsqrtf(var[i] + BN_EPS);
    g_scl[i] = s;
    g_sft[i] = beta[i] - mean[i] * s;
}

// Convert x (fp32) -> bf16 hi/lo planes (layer-0 GEMM input)
__global__ void k_xconv(const float4* __restrict__ x) {
    int i = blockIdx.x * blockDim.x + threadIdx.x;   // float4 index
    if (i >= NN * 32) return;
    float4 v = __ldg(&x[i]);
    uint2 hi, lo;
    split4(v.x, v.y, v.z, v.w, hi, lo);
    ((uint2*)g_Ah)[i] = hi;
    ((uint2*)g_Al)[i] = lo;
}

// ---------------------------------------------------------------------------
// Tensor-core GEMM (unchanged from R15 WIN): A fragments direct from global,
// W hi/lo resident in smem, dual accumulator chains.
// ---------------------------------------------------------------------------
__global__ __launch_bounds__(256)
void k_gemm_tc(const float* __restrict__ W)
{
    extern __shared__ __nv_bfloat16 sm[];
    __nv_bfloat16* sWh = sm;                  // [128][SROW]
    __nv_bfloat16* sWl = sm + 128 * SROW;

    int tid = threadIdx.x;

    for (int idx = tid; idx < 128 * 32; idx += 256) {
        int row = idx >> 5, c0 = (idx & 31) << 2;
        float4 w = __ldg((const float4*)(W + row * DD + c0));
        uint2 hi, lo;
        split4(w.x, w.y, w.z, w.w, hi, lo);
        *(uint2*)(sWh + row * SROW + c0) = hi;
        *(uint2*)(sWl + row * SROW + c0) = lo;
    }
    __syncthreads();

    int wid = tid >> 5;
    int row0 = blockIdx.x * 128 + wid * 16;

    wmma::fragment<wmma::matrix_a, 16, 16, 16, __nv_bfloat16, wmma::row_major> fah[8], fal[8];
    #pragma unroll
    for (int k = 0; k < 8; k++) {
        wmma::load_matrix_sync(fah[k], g_Ah + (size_t)row0 * DD + k * 16, DD);
        wmma::load_matrix_sync(fal[k], g_Al + (size_t)row0 * DD + k * 16, DD);
    }

    float* outbase = g_hl + (size_t)row0 * DD;
    #pragma unroll
    for (int nn = 0; nn < 8; nn++) {
        wmma::fragment<wmma::accumulator, 16, 16, 16, float> acc_hh, acc_ml;
        wmma::fill_fragment(acc_hh, 0.f);
        wmma::fill_fragment(acc_ml, 0.f);
        #pragma unroll
        for (int k = 0; k < 8; k++) {
            wmma::fragment<wmma::matrix_b, 16, 16, 16, __nv_bfloat16, wmma::col_major> fbh, fbl;
            wmma::load_matrix_sync(fbh, sWh + (nn * 16) * SROW + k * 16, SROW);
            wmma::load_matrix_sync(fbl, sWl + (nn * 16) * SROW + k * 16, SROW);
            wmma::mma_sync(acc_hh, fah[k], fbh, acc_hh);
            wmma::mma_sync(acc_ml, fah[k], fbl, acc_ml);
            wmma::mma_sync(acc_ml, fal[k], fbh, acc_ml);
        }
        #pragma unroll
        for (int q = 0; q < acc_hh.num_elements; q++)
            acc_hh.x[q] += acc_ml.x[q];
        wmma::store_matrix_sync(outbase + nn * 16, acc_hh, DD, wmma::mem_row_major);
    }
}

// ---------------------------------------------------------------------------
// CSR aggregation: single node per warp, 4-deep pipeline, persistent warps,
// __launch_bounds__(256, 4) to force >=4 blocks/SM (latency hiding).
// Epilogue: this layer's BN (+relu, bf16 planes) or final BN -> fp32 out.
// ---------------------------------------------------------------------------
__device__ __forceinline__ void acc_edge2(float4& acc, float4 h, unsigned int a,
                                          float nrm, float4 b4) {
    acc.x += fmaxf(h.x + b4.x + (float)( a       & 3u), 0.f) * nrm;
    acc.y += fmaxf(h.y + b4.y + (float)((a >> 2) & 3u), 0.f) * nrm;
    acc.z += fmaxf(h.z + b4.z + (float)((a >> 4) & 3u), 0.f) * nrm;
    acc.w += fmaxf(h.w + b4.w + (float)((a >> 6) & 3u), 0.f) * nrm;
}

__global__ __launch_bounds__(256, 4)
void k_edge_csr(const float* __restrict__ bias, const float* __restrict__ root,
                float* __restrict__ outp, int bnoff)
{
    int gw   = (blockIdx.x * blockDim.x + threadIdx.x) >> 5;
    int lane = threadIdx.x & 31;
    const int nwarps = EDGE_BLOCKS * 8;

    const float4* hl4 = (const float4*)g_hl;
    float4 b4 = __ldg((const float4*)bias + lane);
    float4 rt = __ldg((const float4*)root + lane);
    float4 sc = *(const float4*)&g_scl[bnoff + lane * 4];
    float4 sf = *(const float4*)&g_sft[bnoff + lane * 4];

    for (int n = gw; n < NN; n += nwarps) {
        int beg = __ldg(&g_off[n]);
        int end = __ldg(&g_off[n + 1]);

        float4 acc = make_float4(0.f, 0.f, 0.f, 0.f);
        int j = beg;
        for (; j + 3 < end; j += 4) {
            int s0 = __ldg(&g_srcn[j + 0]);
            int s1 = __ldg(&g_srcn[j + 1]);
            int s2 = __ldg(&g_srcn[j + 2]);
            int s3 = __ldg(&g_srcn[j + 3]);
            float n0 = __ldg(&g_enorm[j + 0]);
            float n1 = __ldg(&g_enorm[j + 1]);
            float n2 = __ldg(&g_enorm[j + 2]);
            float n3 = __ldg(&g_enorm[j + 3]);
            unsigned int a0 = __ldg(&g_ea[(size_t)(j + 0) * 32 + lane]);
            unsigned int a1 = __ldg(&g_ea[(size_t)(j + 1) * 32 + lane]);
            unsigned int a2 = __ldg(&g_ea[(size_t)(j + 2) * 32 + lane]);
            unsigned int a3 = __ldg(&g_ea[(size_t)(j + 3) * 32 + lane]);
            float4 h0 = __ldg(hl4 + (size_t)s0 * 32 + lane);
            float4 h1 = __ldg(hl4 + (size_t)s1 * 32 + lane);
            float4 h2 = __ldg(hl4 + (size_t)s2 * 32 + lane);
            float4 h3 = __ldg(hl4 + (size_t)s3 * 32 + lane);
            acc_edge2(acc, h0, a0, n0, b4);
            acc_edge2(acc, h1, a1, n1, b4);
            acc_edge2(acc, h2, a2, n2, b4);
            acc_edge2(acc, h3, a3, n3, b4);
        }
        for (; j < end; ++j) {
            int s0 = __ldg(&g_srcn[j]);
            float n0 = __ldg(&g_enorm[j]);
            unsigned int a0 = __ldg(&g_ea[(size_t)j * 32 + lane]);
            float4 h0 = __ldg(hl4 + (size_t)s0 * 32 + lane);
            acc_edge2(acc, h0, a0, n0, b4);
        }

        // self-loop: relu(hl + bias + root) * invdeg
        float4 hs = __ldg(hl4 + (size_t)n * 32 + lane);
        float  id = __ldg(&g_invdeg[n]);
        acc.x += fmaxf(hs.x + b4.x + rt.x, 0.f) * id;
        acc.y += fmaxf(hs.y + b4.y + rt.y, 0.f) * id;
        acc.z += fmaxf(hs.z + b4.z + rt.z, 0.f) * id;
        acc.w += fmaxf(hs.w + b4.w + rt.w, 0.f) * id;

        // BN of this layer
        acc.x = fmaf(acc.x, sc.x, sf.x);
        acc.y = fmaf(acc.y, sc.y, sf.y);
        acc.z = fmaf(acc.z, sc.z, sf.z);
        acc.w = fmaf(acc.w, sc.w, sf.w);

        if (outp) {                       // last layer: no relu, fp32 out
            ((float4*)outp)[(size_t)n * 32 + lane] = acc;
        } else {                          // relu + bf16 hi/lo planes
            acc.x = fmaxf(acc.x, 0.f);
            acc.y = fmaxf(acc.y, 0.f);
            acc.z = fmaxf(acc.z, 0.f);
            acc.w = fmaxf(acc.w, 0.f);
            uint2 hi, lo;
            split4(acc.x, acc.y, acc.z, acc.w, hi, lo);
            ((uint2*)g_Ah)[(size_t)n * 32 + lane] = hi;
            ((uint2*)g_Al)[(size_t)n * 32 + lane] = lo;
        }
    }
}

// ---------------------------------------------------------------------------
// Host driver (graph-capturable)
// ---------------------------------------------------------------------------
extern "C" void kernel_launch(void* const* d_in, const int* in_sizes, int n_in,
                              void* d_out, int out_size)
{
    const float* x     = (const float*)d_in[0];
    const void*  ei    = d_in[1];
    const int*   ea    = (const int*)d_in[2];
    const float* W     = (const float*)d_in[3];
    const float* b     = (const float*)d_in[4];
    const float* root  = (const float*)d_in[5];
    const float* gamma = (const float*)d_in[6];
    const float* beta  = (const float*)d_in[7];
    const float* mean  = (const float*)d_in[8];
    const float* var   = (const float*)d_in[9];
    (void)in_sizes; (void)n_in; (void)out_size;

    const int smem_bytes = 2 * 128 * SROW * (int)sizeof(__nv_bfloat16); // 69632
    cudaFuncSetAttribute(k_gemm_tc, cudaFuncAttributeMaxDynamicSharedMemorySize, smem_bytes);

    k_detect<<<1, 256>>>((const int*)ei);
    k_zero<<<(NN + 255) / 256, 256>>>();
    k_edge_pre<<<(EE + 255) / 256, 256>>>(ei);
    k_node<<<(NN + 255) / 256, 256>>>();
    k_scan1<<<98, 1024>>>();
    k_scan2<<<1, 128>>>();
    k_scan3<<<98, 1024>>>();
    k_place<<<(EE + 255) / 256, 256>>>(ei);
    k_pack2<<<(EE * 8 + 255) / 256, 256>>>((const int4*)ea);
    k_bnconst<<<(LL * DD + 255) / 256, 256>>>(gamma, beta, mean, var);
    k_xconv<<<(NN * 32 + 255) / 256, 256>>>((const float4*)x);

    for (int l = 0; l < LL; ++l) {
        k_gemm_tc<<<NT, 256, smem_bytes>>>(W + (size_t)l * DD * DD);
        float* outp = (l == LL - 1) ? (float*)d_out : nullptr;
        k_edge_csr<<<EDGE_BLOCKS, 256>>>(b + (size_t)l * DD, root + (size_t)l * DD,
                                         outp, l * DD);
    }
}

// round 17
// speedup vs baseline: 1.3226x; 1.0735x over previous
#include <cuda_runtime.h>
#include <cuda_bf16.h>
#include <mma.h>
#include <cstdint>
#include <cstddef>

using namespace nvcuda;

#define NN 100000
#define EE 600000
#define DD 128
#define LL 5
#define BN_EPS 1e-5f
#define NT 782
#define NPAD (NT * 128)
#define SROW 136
#define EDGE_BLOCKS 592

// ---------------------------------------------------------------------------
// Device scratch
// ---------------------------------------------------------------------------
__device__ __align__(16) float         g_hl[(size_t)NPAD * DD];   // GEMM out (fp32)
__device__ __align__(16) __nv_bfloat16 g_Ah[(size_t)NPAD * DD];   // GEMM in, hi plane
__device__ __align__(16) __nv_bfloat16 g_Al[(size_t)NPAD * DD];   // GEMM in, lo plane
__device__ __align__(16) __nv_bfloat16 g_Wh[(size_t)LL * DD * DD]; // W hi planes
__device__ __align__(16) __nv_bfloat16 g_Wl[(size_t)LL * DD * DD]; // W lo planes
__device__ __align__(16) unsigned char g_ea[(size_t)EE * 32];     // 2-bit attr, CSR
__device__ __align__(16) int           g_srcn[EE];
__device__ __align__(16) float         g_enorm[EE];
__device__ __align__(16) int           g_pos[EE];
__device__ __align__(16) int           g_degcnt[NN];
__device__ __align__(16) int           g_indeg[NN];
__device__ __align__(16) int           g_cursor[NN];
__device__ __align__(16) int           g_off[NN + 1];
__device__ __align__(16) int           g_bsum[128];
__device__ __align__(16) float         g_invdeg[NN];
__device__ __align__(16) float         g_dinv[NN];
__device__ __align__(16) float         g_scl[LL * DD];
__device__ __align__(16) float         g_sft[LL * DD];
__device__ int g_is64;

__device__ __forceinline__ void split4(float v0, float v1, float v2, float v3,
                                       uint2& hi, uint2& lo) {
    __nv_bfloat162 p0 = __floats2bfloat162_rn(v0, v1);
    __nv_bfloat162 p1 = __floats2bfloat162_rn(v2, v3);
    float2 f0 = __bfloat1622float2(p0);
    float2 f1 = __bfloat1622float2(p1);
    __nv_bfloat162 q0 = __floats2bfloat162_rn(v0 - f0.x, v1 - f0.y);
    __nv_bfloat162 q1 = __floats2bfloat162_rn(v2 - f1.x, v3 - f1.y);
    hi = make_uint2(*(uint32_t*)&p0, *(uint32_t*)&p1);
    lo = make_uint2(*(uint32_t*)&q0, *(uint32_t*)&q1);
}

// ---------------------------------------------------------------------------
// Preprocessing
// ---------------------------------------------------------------------------
__global__ void k_detect(const int* __restrict__ ei32) {
    __shared__ int s_any;
    if (threadIdx.x == 0) s_any = 0;
    __syncthreads();
    int v = 0;
    for (int i = threadIdx.x; i < 4096; i += blockDim.x)
        v |= ei32[2 * i + 1];
    atomicOr(&s_any, v);
    __syncthreads();
    if (threadIdx.x == 0) g_is64 = (s_any == 0) ? 1 : 0;
}

__global__ void k_zero() {
    int i = blockIdx.x * blockDim.x + threadIdx.x;
    if (i < NN) { g_degcnt[i] = 0; g_indeg[i] = 0; g_cursor[i] = 0; }
}

__device__ __forceinline__ void load_edge(const void* ei, int e, int& r, int& c) {
    if (g_is64) {
        const long long* p = (const long long*)ei;
        r = (int)p[e]; c = (int)p[EE + e];
    } else {
        const int* p = (const int*)ei;
        r = p[e]; c = p[EE + e];
    }
    r = min(max(r, 0), NN - 1);
    c = min(max(c, 0), NN - 1);
}

__global__ void k_edge_pre(const void* __restrict__ ei) {
    int e = blockIdx.x * blockDim.x + threadIdx.x;
    if (e >= EE) return;
    int r, c; load_edge(ei, e, r, c);
    atomicAdd(&g_degcnt[r], 1);
    atomicAdd(&g_indeg[c], 1);
}

__global__ void k_node() {
    int n = blockIdx.x * blockDim.x + threadIdx.x;
    if (n >= NN) return;
    float d = (float)(g_degcnt[n] + 1);
    g_invdeg[n] = 1.0f / d;
    g_dinv[n]   = rsqrtf(d);
}

__global__ void k_scan1() {            // grid 98, block 1024
    __shared__ int s[1024];
    int i = blockIdx.x * 1024 + threadIdx.x;
    int v = (i < NN) ? g_indeg[i] : 0;
    s[threadIdx.x] = v;
    __syncthreads();
    for (int d = 1; d < 1024; d <<= 1) {
        int t = (threadIdx.x >= d) ? s[threadIdx.x - d] : 0;
        __syncthreads();
        s[threadIdx.x] += t;
        __syncthreads();
    }
    if (i < NN) g_off[i] = s[threadIdx.x] - v;
    if (threadIdx.x == 1023) g_bsum[blockIdx.x] = s[1023];
}

__global__ void k_scan2() {            // 1 block, 128 threads
    __shared__ int s[128];
    int t = threadIdx.x;
    s[t] = (t < 98) ? g_bsum[t] : 0;
    __syncthreads();
    for (int d = 1; d < 128; d <<= 1) {
        int v = (t >= d) ? s[t - d] : 0;
        __syncthreads();
        s[t] += v;
        __syncthreads();
    }
    if (t < 98) g_bsum[t] = s[t];
}

__global__ void k_scan3() {            // grid 98, block 1024
    int i = blockIdx.x * 1024 + threadIdx.x;
    int add = (blockIdx.x > 0) ? g_bsum[blockIdx.x - 1] : 0;
    if (i < NN) g_off[i] += add;
    if (i == NN) g_off[NN] = EE;
}

__global__ void k_place(const void* __restrict__ ei) {
    int e = blockIdx.x * blockDim.x + threadIdx.x;
    if (e >= EE) return;
    int r, c; load_edge(ei, e, r, c);
    int pos = g_off[c] + atomicAdd(&g_cursor[c], 1);
    g_srcn[pos]  = r;
    g_enorm[pos] = g_dinv[r] * g_dinv[c];
    g_pos[e]     = pos;
}

__global__ void k_pack2(const int4* __restrict__ ea) {
    int i = blockIdx.x * blockDim.x + threadIdx.x;
    if (i >= EE * 8) return;
    int e = i >> 3, g = i & 7;
    const int4* p = ea + (size_t)e * 32 + g * 4;
    unsigned int u = 0;
    #pragma unroll
    for (int q = 0; q < 4; q++) {
        int4 v = __ldg(&p[q]);
        u |= ((unsigned)v.x & 3u) << (q * 8 + 0);
        u |= ((unsigned)v.y & 3u) << (q * 8 + 2);
        u |= ((unsigned)v.z & 3u) << (q * 8 + 4);
        u |= ((unsigned)v.w & 3u) << (q * 8 + 6);
    }
    ((unsigned int*)g_ea)[(size_t)g_pos[e] * 8 + g] = u;
}

__global__ void k_bnconst(const float* __restrict__ gamma, const float* __restrict__ beta,
                          const float* __restrict__ mean,  const float* __restrict__ var) {
    int i = blockIdx.x * blockDim.x + threadIdx.x;
    if (i >= LL * DD) return;
    float s = gamma[i] * rsqrtf(var[i] + BN_EPS);
    g_scl[i] = s;
    g_sft[i] = beta[i] - mean[i] * s;
}

// Convert x (fp32) -> bf16 hi/lo planes (layer-0 GEMM input)
__global__ void k_xconv(const float4* __restrict__ x) {
    int i = blockIdx.x * blockDim.x + threadIdx.x;
    if (i >= NN * 32) return;
    float4 v = __ldg(&x[i]);
    uint2 hi, lo;
    split4(v.x, v.y, v.z, v.w, hi, lo);
    ((uint2*)g_Ah)[i] = hi;
    ((uint2*)g_Al)[i] = lo;
}

// Convert all 5 W matrices -> bf16 hi/lo planes (once per launch)
__global__ void k_wconv(const float4* __restrict__ W) {
    int i = blockIdx.x * blockDim.x + threadIdx.x;   // float4 index
    if (i >= LL * DD * DD / 4) return;
    float4 v = __ldg(&W[i]);
    uint2 hi, lo;
    split4(v.x, v.y, v.z, v.w, hi, lo);
    ((uint2*)g_Wh)[i] = hi;
    ((uint2*)g_Wl)[i] = lo;
}

// ---------------------------------------------------------------------------
// Tensor-core GEMM: A fragments direct from global bf16 planes; W bf16 planes
// bulk-copied (uint4) from global to smem — no convert, half the prologue.
// ---------------------------------------------------------------------------
__global__ __launch_bounds__(256)
void k_gemm_tc(int l)
{
    extern __shared__ __nv_bfloat16 sm[];
    __nv_bfloat16* sWh = sm;                  // [128][SROW]
    __nv_bfloat16* sWl = sm + 128 * SROW;

    int tid = threadIdx.x;
    const __nv_bfloat16* Wh = g_Wh + (size_t)l * DD * DD;
    const __nv_bfloat16* Wl = g_Wl + (size_t)l * DD * DD;

    // 128 rows x 16 uint4 (8 bf16 each) per plane
    for (int idx = tid; idx < 128 * 16; idx += 256) {
        int row = idx >> 4, c0 = (idx & 15) << 3;
        *(uint4*)(sWh + row * SROW + c0) = __ldg((const uint4*)(Wh + row * DD + c0));
        *(uint4*)(sWl + row * SROW + c0) = __ldg((const uint4*)(Wl + row * DD + c0));
    }
    __syncthreads();

    int wid = tid >> 5;
    int row0 = blockIdx.x * 128 + wid * 16;

    wmma::fragment<wmma::matrix_a, 16, 16, 16, __nv_bfloat16, wmma::row_major> fah[8], fal[8];
    #pragma unroll
    for (int k = 0; k < 8; k++) {
        wmma::load_matrix_sync(fah[k], g_Ah + (size_t)row0 * DD + k * 16, DD);
        wmma::load_matrix_sync(fal[k], g_Al + (size_t)row0 * DD + k * 16, DD);
    }

    float* outbase = g_hl + (size_t)row0 * DD;
    #pragma unroll
    for (int nn = 0; nn < 8; nn++) {
        wmma::fragment<wmma::accumulator, 16, 16, 16, float> acc_hh, acc_ml;
        wmma::fill_fragment(acc_hh, 0.f);
        wmma::fill_fragment(acc_ml, 0.f);
        #pragma unroll
        for (int k = 0; k < 8; k++) {
            wmma::fragment<wmma::matrix_b, 16, 16, 16, __nv_bfloat16, wmma::col_major> fbh, fbl;
            wmma::load_matrix_sync(fbh, sWh + (nn * 16) * SROW + k * 16, SROW);
            wmma::load_matrix_sync(fbl, sWl + (nn * 16) * SROW + k * 16, SROW);
            wmma::mma_sync(acc_hh, fah[k], fbh, acc_hh);
            wmma::mma_sync(acc_ml, fah[k], fbl, acc_ml);
            wmma::mma_sync(acc_ml, fal[k], fbh, acc_ml);
        }
        #pragma unroll
        for (int q = 0; q < acc_hh.num_elements; q++)
            acc_hh.x[q] += acc_ml.x[q];
        wmma::store_matrix_sync(outbase + nn * 16, acc_hh, DD, wmma::mem_row_major);
    }
}

// ---------------------------------------------------------------------------
// CSR aggregation: single node per warp, 6-deep pipeline, persistent warps,
// __launch_bounds__(256, 4). Only b4 held across the loop; rt/sc/sf reloaded
// at node-finish (L1-resident) to keep regs <= 64.
// ---------------------------------------------------------------------------
__device__ __forceinline__ void acc_edge2(float4& acc, float4 h, unsigned int a,
                                          float nrm, float4 b4) {
    acc.x += fmaxf(h.x + b4.x + (float)( a       & 3u), 0.f) * nrm;
    acc.y += fmaxf(h.y + b4.y + (float)((a >> 2) & 3u), 0.f) * nrm;
    acc.z += fmaxf(h.z + b4.z + (float)((a >> 4) & 3u), 0.f) * nrm;
    acc.w += fmaxf(h.w + b4.w + (float)((a >> 6) & 3u), 0.f) * nrm;
}

__global__ __launch_bounds__(256, 4)
void k_edge_csr(const float* __restrict__ bias, const float* __restrict__ root,
                float* __restrict__ outp, int bnoff)
{
    int gw   = (blockIdx.x * blockDim.x + threadIdx.x) >> 5;
    int lane = threadIdx.x & 31;
    const int nwarps = EDGE_BLOCKS * 8;

    const float4* hl4 = (const float4*)g_hl;
    float4 b4 = __ldg((const float4*)bias + lane);

    for (int n = gw; n < NN; n += nwarps) {
        int beg = __ldg(&g_off[n]);
        int end = __ldg(&g_off[n + 1]);

        float4 acc = make_float4(0.f, 0.f, 0.f, 0.f);
        int j = beg;
        for (; j + 5 < end; j += 6) {
            int s0 = __ldg(&g_srcn[j + 0]);
            int s1 = __ldg(&g_srcn[j + 1]);
            int s2 = __ldg(&g_srcn[j + 2]);
            int s3 = __ldg(&g_srcn[j + 3]);
            int s4 = __ldg(&g_srcn[j + 4]);
            int s5 = __ldg(&g_srcn[j + 5]);
            float n0 = __ldg(&g_enorm[j + 0]);
            float n1 = __ldg(&g_enorm[j + 1]);
            float n2 = __ldg(&g_enorm[j + 2]);
            float n3 = __ldg(&g_enorm[j + 3]);
            float n4 = __ldg(&g_enorm[j + 4]);
            float n5 = __ldg(&g_enorm[j + 5]);
            unsigned int a0 = __ldg(&g_ea[(size_t)(j + 0) * 32 + lane]);
            unsigned int a1 = __ldg(&g_ea[(size_t)(j + 1) * 32 + lane]);
            unsigned int a2 = __ldg(&g_ea[(size_t)(j + 2) * 32 + lane]);
            unsigned int a3 = __ldg(&g_ea[(size_t)(j + 3) * 32 + lane]);
            unsigned int a4 = __ldg(&g_ea[(size_t)(j + 4) * 32 + lane]);
            unsigned int a5 = __ldg(&g_ea[(size_t)(j + 5) * 32 + lane]);
            float4 h0 = __ldg(hl4 + (size_t)s0 * 32 + lane);
            float4 h1 = __ldg(hl4 + (size_t)s1 * 32 + lane);
            float4 h2 = __ldg(hl4 + (size_t)s2 * 32 + lane);
            float4 h3 = __ldg(hl4 + (size_t)s3 * 32 + lane);
            float4 h4 = __ldg(hl4 + (size_t)s4 * 32 + lane);
            float4 h5 = __ldg(hl4 + (size_t)s5 * 32 + lane);
            acc_edge2(acc, h0, a0, n0, b4);
            acc_edge2(acc, h1, a1, n1, b4);
            acc_edge2(acc, h2, a2, n2, b4);
            acc_edge2(acc, h3, a3, n3, b4);
            acc_edge2(acc, h4, a4, n4, b4);
            acc_edge2(acc, h5, a5, n5, b4);
        }
        for (; j < end; ++j) {
            int s0 = __ldg(&g_srcn[j]);
            float n0 = __ldg(&g_enorm[j]);
            unsigned int a0 = __ldg(&g_ea[(size_t)j * 32 + lane]);
            float4 h0 = __ldg(hl4 + (size_t)s0 * 32 + lane);
            acc_edge2(acc, h0, a0, n0, b4);
        }

        // self-loop: relu(hl + bias + root) * invdeg   (rt reloaded here)
        float4 hs = __ldg(hl4 + (size_t)n * 32 + lane);
        float4 rt = __ldg((const float4*)root + lane);
        float  id = __ldg(&g_invdeg[n]);
        acc.x += fmaxf(hs.x + b4.x + rt.x, 0.f) * id;
        acc.y += fmaxf(hs.y + b4.y + rt.y, 0.f) * id;
        acc.z += fmaxf(hs.z + b4.z + rt.z, 0.f) * id;
        acc.w += fmaxf(hs.w + b4.w + rt.w, 0.f) * id;

        // BN of this layer (sc/sf reloaded here)
        float4 sc = __ldg((const float4*)&g_scl[bnoff] + lane);
        float4 sf = __ldg((const float4*)&g_sft[bnoff] + lane);
        acc.x = fmaf(acc.x, sc.x, sf.x);
        acc.y = fmaf(acc.y, sc.y, sf.y);
        acc.z = fmaf(acc.z, sc.z, sf.z);
        acc.w = fmaf(acc.w, sc.w, sf.w);

        if (outp) {                       // last layer: no relu, fp32 out
            ((float4*)outp)[(size_t)n * 32 + lane] = acc;
        } else {                          // relu + bf16 hi/lo planes
            acc.x = fmaxf(acc.x, 0.f);
            acc.y = fmaxf(acc.y, 0.f);
            acc.z = fmaxf(acc.z, 0.f);
            acc.w = fmaxf(acc.w, 0.f);
            uint2 hi, lo;
            split4(acc.x, acc.y, acc.z, acc.w, hi, lo);
            ((uint2*)g_Ah)[(size_t)n * 32 + lane] = hi;
            ((uint2*)g_Al)[(size_t)n * 32 + lane] = lo;
        }
    }
}

// ---------------------------------------------------------------------------
// Host driver (graph-capturable)
// ---------------------------------------------------------------------------
extern "C" void kernel_launch(void* const* d_in, const int* in_sizes, int n_in,
                              void* d_out, int out_size)
{
    const float* x     = (const float*)d_in[0];
    const void*  ei    = d_in[1];
    const int*   ea    = (const int*)d_in[2];
    const float* W     = (const float*)d_in[3];
    const float* b     = (const float*)d_in[4];
    const float* root  = (const float*)d_in[5];
    const float* gamma = (const float*)d_in[6];
    const float* beta  = (const float*)d_in[7];
    const float* mean  = (const float*)d_in[8];
    const float* var   = (const float*)d_in[9];
    (void)in_sizes; (void)n_in; (void)out_size;

    const int smem_bytes = 2 * 128 * SROW * (int)sizeof(__nv_bfloat16); // 69632
    cudaFuncSetAttribute(k_gemm_tc, cudaFuncAttributeMaxDynamicSharedMemorySize, smem_bytes);

    k_detect<<<1, 256>>>((const int*)ei);
    k_zero<<<(NN + 255) / 256, 256>>>();
    k_edge_pre<<<(EE + 255) / 256, 256>>>(ei);
    k_node<<<(NN + 255) / 256, 256>>>();
    k_scan1<<<98, 1024>>>();
    k_scan2<<<1, 128>>>();
    k_scan3<<<98, 1024>>>();
    k_place<<<(EE + 255) / 256, 256>>>(ei);
    k_pack2<<<(EE * 8 + 255) / 256, 256>>>((const int4*)ea);
    k_bnconst<<<(LL * DD + 255) / 256, 256>>>(gamma, beta, mean, var);
    k_xconv<<<(NN * 32 + 255) / 256, 256>>>((const float4*)x);
    k_wconv<<<(LL * DD * DD / 4 + 255) / 256, 256>>>((const float4*)W);

    for (int l = 0; l < LL; ++l) {
        k_gemm_tc<<<NT, 256, smem_bytes>>>(l);
        float* outp = (l == LL - 1) ? (float*)d_out : nullptr;
        k_edge_csr<<<EDGE_BLOCKS, 256>>>(b + (size_t)l * DD, root + (size_t)l * DD,
                                         outp, l * DD);
    }
}